// round 1
// baseline (speedup 1.0000x reference)
#include <cuda_runtime.h>
#include <math.h>

// Problem constants
constexpr int kN  = 20000;
constexpr int kG  = 8;
constexpr int kE  = 640000;
constexpr int kC  = 64;
constexpr int kNB = 8;
constexpr int kL  = 3;

// ---------------- device scratch (no allocations allowed) ----------------
__device__ float g_ef[kE * kNB];      // edge radial features
__device__ float g_y1[kE * 3];        // sph harmonics l=1
__device__ float g_mask[kE];
__device__ int   g_snd[kE];
__device__ int   g_rcv[kE];
__device__ int   g_sp[kN];
__device__ int   g_batch[kN];
__device__ float g_s[kN * kC];
__device__ float g_xf[kN * kC];
__device__ float g_v[kN * kC * 3];
__device__ float g_sup[kN * kC];
__device__ float g_vup[kN * kC * 3];
__device__ float g_aggs[kN * kC];
__device__ float g_aggv[kN * kC * 3];
__device__ float g_outs[kL * kN * 9];
__device__ int   g_i64;

__device__ __forceinline__ float silu_f(float x) { return x / (1.0f + expf(-x)); }

// ---------------- int64/int32 layout detection ----------------
__global__ void k_detect(const int* sp_raw) {
    if (threadIdx.x == 0) {
        int f = 1;
        for (int i = 0; i < 128; i++) {
            if (sp_raw[2 * i + 1] != 0) { f = 0; break; }
        }
        g_i64 = f;
    }
}

__global__ void k_conv_nodes(const int* braw, const int* spraw) {
    int n = blockIdx.x * blockDim.x + threadIdx.x;
    if (n >= kN) return;
    int f = g_i64;
    g_batch[n] = f ? braw[2 * n] : braw[n];
    g_sp[n]    = f ? spraw[2 * n] : spraw[n];
}

__global__ void k_conv_edges(const int* eraw) {
    int e = blockIdx.x * blockDim.x + threadIdx.x;
    if (e >= kE) return;
    int f = g_i64;
    g_snd[e] = f ? eraw[2 * e]          : eraw[e];
    g_rcv[e] = f ? eraw[2 * (kE + e)]   : eraw[kE + e];
}

// ---------------- edge geometry: shift, y1, bessel*cutoff ----------------
__global__ void k_geom(const float* __restrict__ pos,
                       const float* __restrict__ cell,
                       const float* __restrict__ Sij) {
    int e = blockIdx.x * blockDim.x + threadIdx.x;
    if (e >= kE) return;
    int snd = g_snd[e], rcv = g_rcv[e];
    int b = g_batch[snd];
    float s0 = Sij[e * 3 + 0], s1 = Sij[e * 3 + 1], s2 = Sij[e * 3 + 2];
    const float* cb = cell + b * 9;
    // shift_j = sum_i Sij_i * cell[b, i, j]
    float sh0 = s0 * cb[0] + s1 * cb[3] + s2 * cb[6];
    float sh1 = s0 * cb[1] + s1 * cb[4] + s2 * cb[7];
    float sh2 = s0 * cb[2] + s1 * cb[5] + s2 * cb[8];
    const float invcut = 1.0f / 6.0f;
    float r0 = (pos[rcv * 3 + 0] - pos[snd * 3 + 0] + sh0) * invcut;
    float r1 = (pos[rcv * 3 + 1] - pos[snd * 3 + 1] + sh1) * invcut;
    float r2 = (pos[rcv * 3 + 2] - pos[snd * 3 + 2] + sh2) * invcut;
    float len = sqrtf(r0 * r0 + r1 * r1 + r2 * r2);
    float mask = (len > 0.0f) ? 1.0f : 0.0f;
    float safe = (len > 0.0f) ? len : 1.0f;
    float inv = 1.0f / safe;
    const float sq3 = 1.7320508075688772f;
    g_y1[e * 3 + 0] = sq3 * r0 * inv;
    g_y1[e * 3 + 1] = sq3 * r1 * inv;
    g_y1[e * 3 + 2] = sq3 * r2 * inv;
    float x = safe;
    float env = (x < 1.0f) ? (1.0f - 6.0f * x * x + 8.0f * x * x * x - 3.0f * x * x * x * x) : 0.0f;
    float fac = 1.4142135623730951f * inv * env * mask;
    const float pi = 3.14159265358979323846f;
#pragma unroll
    for (int nb = 1; nb <= kNB; nb++) {
        g_ef[e * kNB + nb - 1] = fac * sinf(pi * (float)nb * safe);
    }
    g_mask[e] = mask;
}

// ---------------- node init: s = embed, xf = s @ W_x ----------------
__global__ void k_init(const float* __restrict__ Wemb, const float* __restrict__ Wx) {
    int t = blockIdx.x * blockDim.x + threadIdx.x;
    if (t >= kN * kC) return;
    int n = t / kC, c = t % kC;
    int sp = g_sp[n];
    g_s[t] = Wemb[sp * kC + c];
    float a = 0.0f;
#pragma unroll 8
    for (int k = 0; k < kC; k++) a += Wemb[sp * kC + k] * Wx[k * kC + c];
    g_xf[t] = a;
}

__global__ void k_zero_v() {
    int i = blockIdx.x * blockDim.x + threadIdx.x;
    if (i < kN * kC * 3) g_v[i] = 0.0f;
}

__global__ void k_zero_agg() {
    int i = blockIdx.x * blockDim.x + threadIdx.x;
    if (i < kN * kC) g_aggs[i] = 0.0f;
    if (i < kN * kC * 3) g_aggv[i] = 0.0f;
}

// ---------------- per-layer node up-projection ----------------
__global__ void k_up(const float* __restrict__ Ws, const float* __restrict__ Wv) {
    int n = blockIdx.x;
    int o = threadIdx.x;  // 64 threads
    __shared__ float ssh[kC];
    __shared__ float vsh[kC * 3];
    ssh[o] = g_s[n * kC + o];
    vsh[o]       = g_v[n * kC * 3 + o];
    vsh[o + 64]  = g_v[n * kC * 3 + o + 64];
    vsh[o + 128] = g_v[n * kC * 3 + o + 128];
    __syncthreads();
    float su = 0.0f, v0 = 0.0f, v1 = 0.0f, v2 = 0.0f;
#pragma unroll 8
    for (int c = 0; c < kC; c++) {
        su += ssh[c] * Ws[c * kC + o];
        float w = Wv[c * kC + o];
        v0 += vsh[c * 3 + 0] * w;
        v1 += vsh[c * 3 + 1] * w;
        v2 += vsh[c * 3 + 2] * w;
    }
    g_sup[n * kC + o] = su;
    g_vup[n * kC * 3 + o * 3 + 0] = v0;
    g_vup[n * kC * 3 + o * 3 + 1] = v1;
    g_vup[n * kC * 3 + o * 3 + 2] = v2;
}

// ---------------- per-layer edge MLP + messages + scatter ----------------
// dyn smem layout: Wr1(512) br1(64) Wr2(4096) br2(64) Wr3(16384) h1(8*64) h2(8*64)
constexpr int SMEM_EDGE = (512 + 64 + 4096 + 64 + 16384 + 512 + 512) * 4;

__global__ void k_edge(const float* __restrict__ Wr1, const float* __restrict__ br1,
                       const float* __restrict__ Wr2, const float* __restrict__ br2,
                       const float* __restrict__ Wr3) {
    extern __shared__ float sm[];
    float* sWr1 = sm;
    float* sbr1 = sWr1 + 512;
    float* sWr2 = sbr1 + 64;
    float* sbr2 = sWr2 + 4096;
    float* sWr3 = sbr2 + 64;
    float* sh1  = sWr3 + 16384;
    float* sh2  = sh1 + 512;

    int tid = threadIdx.x;
    for (int i = tid; i < 512; i += 256) sWr1[i] = Wr1[i];
    if (tid < 64) { sbr1[tid] = br1[tid]; sbr2[tid] = br2[tid]; }
    for (int i = tid; i < 4096; i += 256) sWr2[i] = Wr2[i];
    for (int i = tid; i < 16384; i += 256) sWr3[i] = Wr3[i];
    __syncthreads();

    int warp = tid >> 5;
    int lane = tid & 31;
    int e = blockIdx.x * 8 + warp;
    if (e >= kE) return;

    float ef[8];
#pragma unroll
    for (int i = 0; i < 8; i++) ef[i] = g_ef[e * 8 + i];

    // h1 = silu(ef @ Wr1 + br1)
#pragma unroll
    for (int t = 0; t < 2; t++) {
        int o = lane + 32 * t;
        float a = sbr1[o];
#pragma unroll
        for (int i = 0; i < 8; i++) a += ef[i] * sWr1[i * 64 + o];
        sh1[warp * 64 + o] = silu_f(a);
    }
    __syncwarp();
    // h2 = silu(h1 @ Wr2 + br2)
#pragma unroll
    for (int t = 0; t < 2; t++) {
        int o = lane + 32 * t;
        float a = sbr2[o];
#pragma unroll 8
        for (int k = 0; k < 64; k++) a += sh1[warp * 64 + k] * sWr2[k * 64 + o];
        sh2[warp * 64 + o] = silu_f(a);
    }
    __syncwarp();
    // wts = h2 @ Wr3   (o = t*32 + lane per lane)
    float w[8] = {0, 0, 0, 0, 0, 0, 0, 0};
#pragma unroll 8
    for (int k = 0; k < 64; k++) {
        float h = sh2[warp * 64 + k];
        const float* row = &sWr3[k * 256];
#pragma unroll
        for (int t = 0; t < 8; t++) w[t] += h * row[t * 32 + lane];
    }
    float mask = g_mask[e];
#pragma unroll
    for (int t = 0; t < 8; t++) w[t] *= mask;

    int snd = g_snd[e], rcv = g_rcv[e];
    float y0 = g_y1[e * 3 + 0], y1v = g_y1[e * 3 + 1], y2 = g_y1[e * 3 + 2];
    const float inv_sqrt3 = 0.5773502691896258f;
    const float invavg = 1.0f / 32.0f;

#pragma unroll
    for (int half = 0; half < 2; half++) {
        int c = lane + 32 * half;
        float ss = g_sup[snd * 64 + c];
        float v0 = g_vup[snd * 192 + c * 3 + 0];
        float v1 = g_vup[snd * 192 + c * 3 + 1];
        float v2 = g_vup[snd * 192 + c * 3 + 2];
        float dot = (v0 * y0 + v1 * y1v + v2 * y2) * inv_sqrt3;
        float w0 = w[0 + half], w1 = w[2 + half], w2 = w[4 + half], w3 = w[6 + half];
        float ms = (w0 * ss + w1 * dot) * invavg;
        atomicAdd(&g_aggs[rcv * 64 + c], ms);
        float base = w2 * ss;
        atomicAdd(&g_aggv[rcv * 192 + c * 3 + 0], (base * y0 + w3 * v0) * invavg);
        atomicAdd(&g_aggv[rcv * 192 + c * 3 + 1], (base * y1v + w3 * v1) * invavg);
        atomicAdd(&g_aggv[rcv * 192 + c * 3 + 2], (base * y2 + w3 * v2) * invavg);
    }
}

// ---------------- per-layer node update: msg, sc, product, readout ----------------
__global__ void k_node(const float* __restrict__ Wms, const float* __restrict__ Wmv,
                       const float* __restrict__ Wscs, const float* __restrict__ Wscv,
                       const float* __restrict__ Wps, const float* __restrict__ Wpv,
                       const float* __restrict__ Wread, int l) {
    int n = blockIdx.x;
    int o = threadIdx.x;  // 64 threads
    __shared__ float ags[64], agv[192], sold[64], vold[192], xfs[64];
    __shared__ float ts[64], tv[192], vnew[192];
    ags[o] = g_aggs[n * 64 + o];
    agv[o] = g_aggv[n * 192 + o];
    agv[o + 64] = g_aggv[n * 192 + o + 64];
    agv[o + 128] = g_aggv[n * 192 + o + 128];
    sold[o] = g_s[n * 64 + o];
    vold[o] = g_v[n * 192 + o];
    vold[o + 64] = g_v[n * 192 + o + 64];
    vold[o + 128] = g_v[n * 192 + o + 128];
    xfs[o] = g_xf[n * 64 + o];
    __syncthreads();

    int sp = g_sp[n];
    const float* Wss = Wscs + sp * 4096;
    const float* Wsv = Wscv + sp * 4096;

    float ms = 0, mv0 = 0, mv1 = 0, mv2 = 0;
    float scs = 0, scv0 = 0, scv1 = 0, scv2 = 0;
#pragma unroll 4
    for (int c = 0; c < 64; c++) {
        float a = ags[c];
        ms += a * Wms[c * 64 + o];
        float wm = Wmv[c * 64 + o];
        mv0 += agv[c * 3 + 0] * wm;
        mv1 += agv[c * 3 + 1] * wm;
        mv2 += agv[c * 3 + 2] * wm;
        scs += sold[c] * Wss[c * 64 + o];
        float wv = Wsv[c * 64 + o];
        scv0 += vold[c * 3 + 0] * wv;
        scv1 += vold[c * 3 + 1] * wv;
        scv2 += vold[c * 3 + 2] * wv;
    }
    float xfo = xfs[o];
    ts[o] = xfo * ms;
    tv[o * 3 + 0] = xfo * mv0;
    tv[o * 3 + 1] = xfo * mv1;
    tv[o * 3 + 2] = xfo * mv2;
    __syncthreads();

    float sn = scs, vn0 = scv0, vn1 = scv1, vn2 = scv2;
#pragma unroll 4
    for (int c = 0; c < 64; c++) {
        sn += ts[c] * Wps[c * 64 + o];
        float wp = Wpv[c * 64 + o];
        vn0 += tv[c * 3 + 0] * wp;
        vn1 += tv[c * 3 + 1] * wp;
        vn2 += tv[c * 3 + 2] * wp;
    }
    g_s[n * 64 + o] = sn;
    g_v[n * 192 + o * 3 + 0] = vn0;
    g_v[n * 192 + o * 3 + 1] = vn1;
    g_v[n * 192 + o * 3 + 2] = vn2;
    vnew[o * 3 + 0] = vn0;
    vnew[o * 3 + 1] = vn1;
    vnew[o * 3 + 2] = vn2;
    __syncthreads();

    if (o < 9) {
        int ro = o / 3, m = o % 3;
        float a = 0.0f;
#pragma unroll 8
        for (int c = 0; c < 64; c++) a += vnew[c * 3 + m] * Wread[ro * 64 + c];
        g_outs[l * kN * 9 + n * 9 + o] = a;
    }
}

// ---------------- final: silu over layer-stacked outs, sum, graph reduce ----------------
__global__ void k_final(float* __restrict__ out) {
    __shared__ float acc[72];
    int tid = threadIdx.x;
    if (tid < 72) acc[tid] = 0.0f;
    __syncthreads();
    int n = blockIdx.x * blockDim.x + tid;
    if (n < kN) {
        int b = g_batch[n];
#pragma unroll
        for (int j = 0; j < 9; j++) {
            float x = 0.0f;
#pragma unroll
            for (int l = 0; l < kL; l++) x += silu_f(g_outs[l * kN * 9 + n * 9 + j]);
            atomicAdd(&acc[b * 9 + j], x);
        }
    }
    __syncthreads();
    if (tid < 72) atomicAdd(&out[tid], acc[tid]);
}

// ---------------- launch ----------------
extern "C" void kernel_launch(void* const* d_in, const int* in_sizes, int n_in,
                              void* d_out, int out_size) {
    const float* pos  = (const float*)d_in[0];
    const float* cell = (const float*)d_in[1];
    const float* Sij  = (const float*)d_in[2];
    const float* Wemb = (const float*)d_in[3];
    const float* Wx   = (const float*)d_in[4];
    const float* Wups = (const float*)d_in[5];
    const float* Wupv = (const float*)d_in[6];
    const float* Wr1  = (const float*)d_in[7];
    const float* br1  = (const float*)d_in[8];
    const float* Wr2  = (const float*)d_in[9];
    const float* br2  = (const float*)d_in[10];
    const float* Wr3  = (const float*)d_in[11];
    const float* Wms  = (const float*)d_in[12];
    const float* Wmv  = (const float*)d_in[13];
    const float* Wscs = (const float*)d_in[14];
    const float* Wscv = (const float*)d_in[15];
    const float* Wps  = (const float*)d_in[16];
    const float* Wpv  = (const float*)d_in[17];
    const float* Wread= (const float*)d_in[18];
    const int* ei     = (const int*)d_in[19];
    const int* braw   = (const int*)d_in[20];
    const int* spraw  = (const int*)d_in[21];
    float* out = (float*)d_out;

    cudaFuncSetAttribute(k_edge, cudaFuncAttributeMaxDynamicSharedMemorySize, SMEM_EDGE);

    k_detect<<<1, 32>>>(spraw);
    k_conv_nodes<<<(kN + 255) / 256, 256>>>(braw, spraw);
    k_conv_edges<<<(kE + 255) / 256, 256>>>(ei);
    k_geom<<<(kE + 255) / 256, 256>>>(pos, cell, Sij);
    k_init<<<(kN * kC + 255) / 256, 256>>>(Wemb, Wx);
    k_zero_v<<<(kN * kC * 3 + 255) / 256, 256>>>();
    cudaMemsetAsync(out, 0, 72 * sizeof(float));

    for (int l = 0; l < kL; l++) {
        k_up<<<kN, 64>>>(Wups + l * 4096, Wupv + l * 4096);
        k_zero_agg<<<(kN * kC * 3 + 255) / 256, 256>>>();
        k_edge<<<(kE + 7) / 8, 256, SMEM_EDGE>>>(Wr1 + l * 512, br1 + l * 64,
                                                 Wr2 + l * 4096, br2 + l * 64,
                                                 Wr3 + l * 16384);
        k_node<<<kN, 64>>>(Wms + l * 4096, Wmv + l * 4096,
                           Wscs + l * 32768, Wscv + l * 32768,
                           Wps + l * 4096, Wpv + l * 4096,
                           Wread + l * 192, l);
    }
    k_final<<<(kN + 255) / 256, 256>>>(out);
}

// round 2
// speedup vs baseline: 2.4414x; 2.4414x over previous
#include <cuda_runtime.h>
#include <math.h>

constexpr int kN  = 20000;
constexpr int kG  = 8;
constexpr int kE  = 640000;
constexpr int kC  = 64;
constexpr int kNB = 8;
constexpr int kL  = 3;
constexpr int TE  = 128;   // edges per block in k_edge

// ---------------- device scratch ----------------
__device__ float g_ef[kE * kNB];
__device__ float g_y1[kE * 3];
__device__ float g_mask[kE];
__device__ int   g_snd[kE];
__device__ int   g_rcv[kE];
__device__ int   g_sp[kN];
__device__ int   g_batch[kN];
__device__ float g_s[kN * kC];
__device__ float g_xf[kN * kC];
__device__ float g_xfs[8 * kC];           // per-species xf rows
__device__ float g_v[kN * kC * 3];
__device__ float g_supv[kN * kC * 4];     // (s, v0, v1, v2) interleaved
__device__ float g_agg[kN * kC * 4];      // (aggs, aggv0..2) interleaved
__device__ float g_outs[kL * kN * 9];
__device__ int   g_i64;

typedef unsigned long long ull;

__device__ __forceinline__ float silu_f(float x) { return x / (1.0f + expf(-x)); }

__device__ __forceinline__ ull pack2(float lo, float hi) {
    ull r; asm("mov.b64 %0,{%1,%2};" : "=l"(r) : "f"(lo), "f"(hi)); return r;
}
__device__ __forceinline__ void unpack2(ull v, float& lo, float& hi) {
    asm("mov.b64 {%0,%1},%2;" : "=f"(lo), "=f"(hi) : "l"(v));
}
__device__ __forceinline__ void fma2(ull& d, ull a, ull b) {
    asm("fma.rn.f32x2 %0,%1,%2,%0;" : "+l"(d) : "l"(a), "l"(b));
}
__device__ __forceinline__ void red4(float* p, float a, float b, float c, float d) {
    asm volatile("red.global.add.v4.f32 [%0],{%1,%2,%3,%4};"
                 :: "l"(p), "f"(a), "f"(b), "f"(c), "f"(d) : "memory");
}

// ---------------- int64/int32 detection + conversion ----------------
__global__ void k_detect(const int* sp_raw) {
    if (threadIdx.x == 0) {
        int f = 1;
        for (int i = 0; i < 128; i++)
            if (sp_raw[2 * i + 1] != 0) { f = 0; break; }
        g_i64 = f;
    }
}
__global__ void k_conv_nodes(const int* braw, const int* spraw) {
    int n = blockIdx.x * blockDim.x + threadIdx.x;
    if (n >= kN) return;
    int f = g_i64;
    g_batch[n] = f ? braw[2 * n] : braw[n];
    g_sp[n]    = f ? spraw[2 * n] : spraw[n];
}
__global__ void k_conv_edges(const int* eraw) {
    int e = blockIdx.x * blockDim.x + threadIdx.x;
    if (e >= kE) return;
    int f = g_i64;
    g_snd[e] = f ? eraw[2 * e]        : eraw[e];
    g_rcv[e] = f ? eraw[2 * (kE + e)] : eraw[kE + e];
}

// ---------------- edge geometry ----------------
__global__ void k_geom(const float* __restrict__ pos,
                       const float* __restrict__ cell,
                       const float* __restrict__ Sij) {
    int e = blockIdx.x * blockDim.x + threadIdx.x;
    if (e >= kE) return;
    int snd = g_snd[e], rcv = g_rcv[e];
    int b = g_batch[snd];
    float s0 = Sij[e * 3 + 0], s1 = Sij[e * 3 + 1], s2 = Sij[e * 3 + 2];
    const float* cb = cell + b * 9;
    float sh0 = s0 * cb[0] + s1 * cb[3] + s2 * cb[6];
    float sh1 = s0 * cb[1] + s1 * cb[4] + s2 * cb[7];
    float sh2 = s0 * cb[2] + s1 * cb[5] + s2 * cb[8];
    const float invcut = 1.0f / 6.0f;
    float r0 = (pos[rcv * 3 + 0] - pos[snd * 3 + 0] + sh0) * invcut;
    float r1 = (pos[rcv * 3 + 1] - pos[snd * 3 + 1] + sh1) * invcut;
    float r2 = (pos[rcv * 3 + 2] - pos[snd * 3 + 2] + sh2) * invcut;
    float len = sqrtf(r0 * r0 + r1 * r1 + r2 * r2);
    float mask = (len > 0.0f) ? 1.0f : 0.0f;
    float safe = (len > 0.0f) ? len : 1.0f;
    float inv = 1.0f / safe;
    const float sq3 = 1.7320508075688772f;
    g_y1[e * 3 + 0] = sq3 * r0 * inv;
    g_y1[e * 3 + 1] = sq3 * r1 * inv;
    g_y1[e * 3 + 2] = sq3 * r2 * inv;
    float x = safe;
    float env = (x < 1.0f) ? (1.0f - 6.0f * x * x + 8.0f * x * x * x - 3.0f * x * x * x * x) : 0.0f;
    float fac = 1.4142135623730951f * inv * env * mask;
    const float pi = 3.14159265358979323846f;
#pragma unroll
    for (int nb = 1; nb <= kNB; nb++)
        g_ef[e * kNB + nb - 1] = fac * sinf(pi * (float)nb * safe);
    g_mask[e] = mask;
}

// ---------------- per-species xf rows: xfs[sp] = Wemb[sp] @ Wx ----------------
__global__ void k_spec(const float* __restrict__ Wemb, const float* __restrict__ Wx) {
    int t = threadIdx.x;   // 512 = 8 species * 64 cols
    int sp = t >> 6, c = t & 63;
    float a = 0.0f;
#pragma unroll 8
    for (int k = 0; k < kC; k++) a += Wemb[sp * kC + k] * Wx[k * kC + c];
    g_xfs[t] = a;
}

__global__ void k_init(const float* __restrict__ Wemb) {
    int t = blockIdx.x * blockDim.x + threadIdx.x;
    if (t >= kN * kC) return;
    int n = t / kC, c = t % kC;
    int sp = g_sp[n];
    g_s[t]  = Wemb[sp * kC + c];
    g_xf[t] = g_xfs[sp * kC + c];
}

__global__ void k_zero_v() {
    int i = blockIdx.x * blockDim.x + threadIdx.x;
    if (i < kN * kC * 3) g_v[i] = 0.0f;
}
__global__ void k_zero_agg() {
    int i = blockIdx.x * blockDim.x + threadIdx.x;
    if (i < kN * kC * 4) g_agg[i] = 0.0f;
}

// ---------------- up-projection: supv[n][c][4] = (s@Ws, v@Wv) ----------------
__global__ __launch_bounds__(256) void k_up(const float* __restrict__ Ws,
                                            const float* __restrict__ Wv) {
    __shared__ float sWs[4096], sWv[4096], ss[4][64], sv[4][192];
    int tid = threadIdx.x;
    for (int i = tid; i < 4096; i += 256) { sWs[i] = Ws[i]; sWv[i] = Wv[i]; }
    int slot = tid >> 6, o = tid & 63;
    int n = blockIdx.x * 4 + slot;
    ss[slot][o] = g_s[n * 64 + o];
    sv[slot][o * 3 + 0] = g_v[n * 192 + o * 3 + 0];
    sv[slot][o * 3 + 1] = g_v[n * 192 + o * 3 + 1];
    sv[slot][o * 3 + 2] = g_v[n * 192 + o * 3 + 2];
    __syncthreads();
    float su = 0.0f, v0 = 0.0f, v1 = 0.0f, v2 = 0.0f;
#pragma unroll 8
    for (int c = 0; c < 64; c++) {
        su += ss[slot][c] * sWs[c * 64 + o];
        float w = sWv[c * 64 + o];
        v0 += sv[slot][c * 3 + 0] * w;
        v1 += sv[slot][c * 3 + 1] * w;
        v2 += sv[slot][c * 3 + 2] * w;
    }
    float4 r = make_float4(su, v0, v1, v2);
    *(float4*)&g_supv[n * 256 + o * 4] = r;
}

// ---------------- edge kernel: tiled MLP GEMMs + fused messages ----------------
// smem floats: Wr1 512 | br1 64 | br2 64 | Wr2 4096 | Wr3 16384 | h1 TE*64 | h2 TE*64 | ef TE*8
constexpr int EDGE_SMEM = (512 + 64 + 64 + 4096 + 16384 + TE * 64 + TE * 64 + TE * 8) * 4;

__global__ __launch_bounds__(512, 1) void k_edge(const float* __restrict__ Wr1,
                                                 const float* __restrict__ br1,
                                                 const float* __restrict__ Wr2,
                                                 const float* __restrict__ br2,
                                                 const float* __restrict__ Wr3) {
    extern __shared__ float sm[];
    float* sWr1 = sm;                 // 512
    float* sbr1 = sWr1 + 512;         // 64
    float* sbr2 = sbr1 + 64;          // 64
    float* sWr2 = sbr2 + 64;          // 4096
    float* sWr3 = sWr2 + 4096;        // 16384
    float* sh1  = sWr3 + 16384;       // TE*64
    float* sh2  = sh1 + TE * 64;      // TE*64
    float* sef  = sh2 + TE * 64;      // TE*8

    int tid = threadIdx.x;
    int e0 = blockIdx.x * TE;
    for (int i = tid; i < 512; i += 512) sWr1[i] = Wr1[i];
    if (tid < 64) { sbr1[tid] = br1[tid]; sbr2[tid] = br2[tid]; }
    for (int i = tid; i < 4096; i += 512) sWr2[i] = Wr2[i];
    for (int i = tid; i < 16384; i += 512) sWr3[i] = Wr3[i];
    for (int i = tid; i < TE * 8; i += 512) sef[i] = g_ef[e0 * 8 + i];
    __syncthreads();

    int eg = tid >> 4;            // 0..31 edge groups
    int cq = tid & 15;            // channel quad
    int c0 = cq * 4;
    int eb = eg * 4;              // local edge base (4 edges per thread)

    // ---- h1 = silu(ef @ Wr1 + br1) ----
    {
        ull acc[4][2];
        ull b0 = pack2(sbr1[c0], sbr1[c0 + 1]);
        ull b1 = pack2(sbr1[c0 + 2], sbr1[c0 + 3]);
#pragma unroll
        for (int i = 0; i < 4; i++) { acc[i][0] = b0; acc[i][1] = b1; }
#pragma unroll
        for (int k = 0; k < 8; k++) {
            const ull* wp = (const ull*)&sWr1[k * 64 + c0];
            ull w0 = wp[0], w1 = wp[1];
#pragma unroll
            for (int i = 0; i < 4; i++) {
                float h = sef[(eb + i) * 8 + k];
                ull ha = pack2(h, h);
                fma2(acc[i][0], ha, w0);
                fma2(acc[i][1], ha, w1);
            }
        }
#pragma unroll
        for (int i = 0; i < 4; i++) {
#pragma unroll
            for (int p = 0; p < 2; p++) {
                float lo, hi; unpack2(acc[i][p], lo, hi);
                sh1[(eb + i) * 64 + c0 + 2 * p]     = silu_f(lo);
                sh1[(eb + i) * 64 + c0 + 2 * p + 1] = silu_f(hi);
            }
        }
    }
    __syncthreads();

    // ---- h2 = silu(h1 @ Wr2 + br2) ----
    {
        ull acc[4][2];
        ull b0 = pack2(sbr2[c0], sbr2[c0 + 1]);
        ull b1 = pack2(sbr2[c0 + 2], sbr2[c0 + 3]);
#pragma unroll
        for (int i = 0; i < 4; i++) { acc[i][0] = b0; acc[i][1] = b1; }
#pragma unroll 4
        for (int k = 0; k < 64; k++) {
            const ull* wp = (const ull*)&sWr2[k * 64 + c0];
            ull w0 = wp[0], w1 = wp[1];
#pragma unroll
            for (int i = 0; i < 4; i++) {
                float h = sh1[(eb + i) * 64 + k];
                ull ha = pack2(h, h);
                fma2(acc[i][0], ha, w0);
                fma2(acc[i][1], ha, w1);
            }
        }
#pragma unroll
        for (int i = 0; i < 4; i++) {
#pragma unroll
            for (int p = 0; p < 2; p++) {
                float lo, hi; unpack2(acc[i][p], lo, hi);
                sh2[(eb + i) * 64 + c0 + 2 * p]     = silu_f(lo);
                sh2[(eb + i) * 64 + c0 + 2 * p + 1] = silu_f(hi);
            }
        }
    }
    __syncthreads();

    // ---- wts = h2 @ Wr3, fused with message construction ----
    ull acc3[4][4][2];
#pragma unroll
    for (int i = 0; i < 4; i++)
#pragma unroll
        for (int t = 0; t < 4; t++) { acc3[i][t][0] = 0ULL; acc3[i][t][1] = 0ULL; }

#pragma unroll 2
    for (int k = 0; k < 64; k++) {
        ull ha[4];
#pragma unroll
        for (int i = 0; i < 4; i++) {
            float h = sh2[(eb + i) * 64 + k];
            ha[i] = pack2(h, h);
        }
        const ull* wr = (const ull*)&sWr3[k * 256 + c0];
#pragma unroll
        for (int t = 0; t < 4; t++) {
            ull w0 = wr[t * 32], w1 = wr[t * 32 + 1];
#pragma unroll
            for (int i = 0; i < 4; i++) {
                fma2(acc3[i][t][0], ha[i], w0);
                fma2(acc3[i][t][1], ha[i], w1);
            }
        }
    }

    const float inv_sqrt3 = 0.5773502691896258f;
#pragma unroll
    for (int i = 0; i < 4; i++) {
        int e = e0 + eb + i;
        float msk = g_mask[e] * 0.03125f;   // fold 1/AVG
        float y0 = g_y1[e * 3 + 0], y1v = g_y1[e * 3 + 1], y2 = g_y1[e * 3 + 2];
        int snd = g_snd[e], rcv = g_rcv[e];
        const float4* svp = (const float4*)&g_supv[snd * 256];
        float* agp = &g_agg[rcv * 256];
#pragma unroll
        for (int p = 0; p < 2; p++) {
            float wt[4][2];
#pragma unroll
            for (int t = 0; t < 4; t++) unpack2(acc3[i][t][p], wt[t][0], wt[t][1]);
#pragma unroll
            for (int jj = 0; jj < 2; jj++) {
                int c = c0 + 2 * p + jj;
                float w0 = wt[0][jj] * msk, w1 = wt[1][jj] * msk;
                float w2 = wt[2][jj] * msk, w3 = wt[3][jj] * msk;
                float4 sv = svp[c];
                float dot = (sv.y * y0 + sv.z * y1v + sv.w * y2) * inv_sqrt3;
                float ms  = w0 * sv.x + w1 * dot;
                float a0  = w2 * sv.x;
                float mv0 = a0 * y0  + w3 * sv.y;
                float mv1 = a0 * y1v + w3 * sv.z;
                float mv2 = a0 * y2  + w3 * sv.w;
                red4(agp + c * 4, ms, mv0, mv1, mv2);
            }
        }
    }
}

// ---------------- node update: msg, sc, product, readout ----------------
// dyn smem floats: Wms 4096 | Wmv 4096 | Wps 4096 | Wpv 4096 | agg 4*64*4 | sold 4*64
//                  vold 4*192 | ts 4*64 | tv 4*192 | vnew 4*192
constexpr int NODE_SMEM = (4 * 4096 + 1024 + 256 + 768 + 256 + 768 + 768) * 4;

__global__ __launch_bounds__(256) void k_node(const float* __restrict__ Wms,
                                              const float* __restrict__ Wmv,
                                              const float* __restrict__ Wscs,
                                              const float* __restrict__ Wscv,
                                              const float* __restrict__ Wps,
                                              const float* __restrict__ Wpv,
                                              const float* __restrict__ Wread, int l) {
    extern __shared__ float sm[];
    float* sWms = sm;
    float* sWmv = sWms + 4096;
    float* sWps = sWmv + 4096;
    float* sWpv = sWps + 4096;
    float* sagg = sWpv + 4096;   // [4][64][4]
    float* sold = sagg + 1024;   // [4][64]
    float* vold = sold + 256;    // [4][192]
    float* sts  = vold + 768;    // [4][64]
    float* stv  = sts + 256;     // [4][192]
    float* vnew = stv + 768;     // [4][192]

    int tid = threadIdx.x;
    for (int i = tid; i < 4096; i += 256) {
        sWms[i] = Wms[i]; sWmv[i] = Wmv[i]; sWps[i] = Wps[i]; sWpv[i] = Wpv[i];
    }
    int slot = tid >> 6, o = tid & 63;
    int n = blockIdx.x * 4 + slot;
    *(float4*)&sagg[slot * 256 + o * 4] = *(const float4*)&g_agg[n * 256 + o * 4];
    sold[slot * 64 + o] = g_s[n * 64 + o];
    vold[slot * 192 + o * 3 + 0] = g_v[n * 192 + o * 3 + 0];
    vold[slot * 192 + o * 3 + 1] = g_v[n * 192 + o * 3 + 1];
    vold[slot * 192 + o * 3 + 2] = g_v[n * 192 + o * 3 + 2];
    __syncthreads();

    int sp = g_sp[n];
    const float* Wss = Wscs + sp * 4096;
    const float* Wsv = Wscv + sp * 4096;

    float ms = 0, mv0 = 0, mv1 = 0, mv2 = 0;
    float scs = 0, scv0 = 0, scv1 = 0, scv2 = 0;
#pragma unroll 4
    for (int c = 0; c < 64; c++) {
        const float* ag = &sagg[slot * 256 + c * 4];
        ms  += ag[0] * sWms[c * 64 + o];
        float wm = sWmv[c * 64 + o];
        mv0 += ag[1] * wm; mv1 += ag[2] * wm; mv2 += ag[3] * wm;
        scs += sold[slot * 64 + c] * Wss[c * 64 + o];
        float wv = Wsv[c * 64 + o];
        scv0 += vold[slot * 192 + c * 3 + 0] * wv;
        scv1 += vold[slot * 192 + c * 3 + 1] * wv;
        scv2 += vold[slot * 192 + c * 3 + 2] * wv;
    }
    float xfo = g_xf[n * 64 + o];
    sts[slot * 64 + o] = xfo * ms;
    stv[slot * 192 + o * 3 + 0] = xfo * mv0;
    stv[slot * 192 + o * 3 + 1] = xfo * mv1;
    stv[slot * 192 + o * 3 + 2] = xfo * mv2;
    __syncthreads();

    float sn = scs, vn0 = scv0, vn1 = scv1, vn2 = scv2;
#pragma unroll 4
    for (int c = 0; c < 64; c++) {
        sn += sts[slot * 64 + c] * sWps[c * 64 + o];
        float wp = sWpv[c * 64 + o];
        vn0 += stv[slot * 192 + c * 3 + 0] * wp;
        vn1 += stv[slot * 192 + c * 3 + 1] * wp;
        vn2 += stv[slot * 192 + c * 3 + 2] * wp;
    }
    g_s[n * 64 + o] = sn;
    g_v[n * 192 + o * 3 + 0] = vn0;
    g_v[n * 192 + o * 3 + 1] = vn1;
    g_v[n * 192 + o * 3 + 2] = vn2;
    vnew[slot * 192 + o * 3 + 0] = vn0;
    vnew[slot * 192 + o * 3 + 1] = vn1;
    vnew[slot * 192 + o * 3 + 2] = vn2;
    __syncthreads();

    if (o < 9) {
        int ro = o / 3, m = o % 3;
        float a = 0.0f;
#pragma unroll 8
        for (int c = 0; c < 64; c++) a += vnew[slot * 192 + c * 3 + m] * Wread[ro * 64 + c];
        g_outs[l * kN * 9 + n * 9 + o] = a;
    }
}

// ---------------- final reduce ----------------
__global__ void k_final(float* __restrict__ out) {
    __shared__ float acc[72];
    int tid = threadIdx.x;
    if (tid < 72) acc[tid] = 0.0f;
    __syncthreads();
    int n = blockIdx.x * blockDim.x + tid;
    if (n < kN) {
        int b = g_batch[n];
#pragma unroll
        for (int j = 0; j < 9; j++) {
            float x = 0.0f;
#pragma unroll
            for (int l = 0; l < kL; l++) x += silu_f(g_outs[l * kN * 9 + n * 9 + j]);
            atomicAdd(&acc[b * 9 + j], x);
        }
    }
    __syncthreads();
    if (tid < 72) atomicAdd(&out[tid], acc[tid]);
}

// ---------------- launch ----------------
extern "C" void kernel_launch(void* const* d_in, const int* in_sizes, int n_in,
                              void* d_out, int out_size) {
    const float* pos  = (const float*)d_in[0];
    const float* cell = (const float*)d_in[1];
    const float* Sij  = (const float*)d_in[2];
    const float* Wemb = (const float*)d_in[3];
    const float* Wx   = (const float*)d_in[4];
    const float* Wups = (const float*)d_in[5];
    const float* Wupv = (const float*)d_in[6];
    const float* Wr1  = (const float*)d_in[7];
    const float* br1  = (const float*)d_in[8];
    const float* Wr2  = (const float*)d_in[9];
    const float* br2  = (const float*)d_in[10];
    const float* Wr3  = (const float*)d_in[11];
    const float* Wms  = (const float*)d_in[12];
    const float* Wmv  = (const float*)d_in[13];
    const float* Wscs = (const float*)d_in[14];
    const float* Wscv = (const float*)d_in[15];
    const float* Wps  = (const float*)d_in[16];
    const float* Wpv  = (const float*)d_in[17];
    const float* Wread= (const float*)d_in[18];
    const int* ei     = (const int*)d_in[19];
    const int* braw   = (const int*)d_in[20];
    const int* spraw  = (const int*)d_in[21];
    float* out = (float*)d_out;

    cudaFuncSetAttribute(k_edge, cudaFuncAttributeMaxDynamicSharedMemorySize, EDGE_SMEM);
    cudaFuncSetAttribute(k_node, cudaFuncAttributeMaxDynamicSharedMemorySize, NODE_SMEM);

    k_detect<<<1, 32>>>(spraw);
    k_conv_nodes<<<(kN + 255) / 256, 256>>>(braw, spraw);
    k_conv_edges<<<(kE + 255) / 256, 256>>>(ei);
    k_geom<<<(kE + 255) / 256, 256>>>(pos, cell, Sij);
    k_spec<<<1, 512>>>(Wemb, Wx);
    k_init<<<(kN * kC + 255) / 256, 256>>>(Wemb);
    k_zero_v<<<(kN * kC * 3 + 255) / 256, 256>>>();
    cudaMemsetAsync(out, 0, 72 * sizeof(float));

    for (int l = 0; l < kL; l++) {
        k_up<<<kN / 4, 256>>>(Wups + l * 4096, Wupv + l * 4096);
        k_zero_agg<<<(kN * kC * 4 + 255) / 256, 256>>>();
        k_edge<<<kE / TE, 512, EDGE_SMEM>>>(Wr1 + l * 512, br1 + l * 64,
                                            Wr2 + l * 4096, br2 + l * 64,
                                            Wr3 + l * 16384);
        k_node<<<kN / 4, 256, NODE_SMEM>>>(Wms + l * 4096, Wmv + l * 4096,
                                           Wscs + l * 32768, Wscv + l * 32768,
                                           Wps + l * 4096, Wpv + l * 4096,
                                           Wread + l * 192, l);
    }
    k_final<<<(kN + 255) / 256, 256>>>(out);
}

// round 3
// speedup vs baseline: 2.9443x; 1.2060x over previous
#include <cuda_runtime.h>
#include <math.h>

constexpr int kN  = 20000;
constexpr int kG  = 8;
constexpr int kE  = 640000;
constexpr int kC  = 64;
constexpr int kNB = 8;
constexpr int kL  = 3;
constexpr int TE  = 128;          // edges per tile in k_edge
constexpr int NTILE = kE / TE;    // 5000
constexpr int EGRID = 152;        // persistent blocks (GB300: 152 SMs)

// ---------------- device scratch ----------------
__device__ float g_ef[kE * kNB];
__device__ float g_y1[kE * 3];
__device__ float g_mask[kE];
__device__ int   g_snd[kE];
__device__ int   g_rcv[kE];
__device__ int   g_sp[kN];
__device__ int   g_batch[kN];
__device__ float g_s[kN * kC];
__device__ float g_xf[kN * kC];
__device__ float g_xfs[8 * kC];
__device__ float g_v[kN * kC * 3];
__device__ float g_supv[kN * kC * 4];   // (s, v0, v1, v2)
__device__ float g_agg[kN * kC * 4];    // (aggs, aggv0..2)
__device__ float g_outs[kL * kN * 9];
__device__ int   g_i64;

typedef unsigned long long ull;

__device__ __forceinline__ float silu_f(float x) {
    return __fdividef(x, 1.0f + __expf(-x));
}
__device__ __forceinline__ ull pack2(float lo, float hi) {
    ull r; asm("mov.b64 %0,{%1,%2};" : "=l"(r) : "f"(lo), "f"(hi)); return r;
}
__device__ __forceinline__ void unpack2(ull v, float& lo, float& hi) {
    asm("mov.b64 {%0,%1},%2;" : "=f"(lo), "=f"(hi) : "l"(v));
}
__device__ __forceinline__ void fma2(ull& d, ull a, ull b) {
    asm("fma.rn.f32x2 %0,%1,%2,%0;" : "+l"(d) : "l"(a), "l"(b));
}
__device__ __forceinline__ void red4(float* p, float a, float b, float c, float d) {
    asm volatile("red.global.add.v4.f32 [%0],{%1,%2,%3,%4};"
                 :: "l"(p), "f"(a), "f"(b), "f"(c), "f"(d) : "memory");
}

// ---------------- detect int width + per-species xf rows ----------------
__global__ void k_detect_spec(const int* sp_raw, const float* __restrict__ Wemb,
                              const float* __restrict__ Wx) {
    int t = threadIdx.x;       // 512
    if (t == 0) {
        int f = 1;
        for (int i = 0; i < 128; i++)
            if (sp_raw[2 * i + 1] != 0) { f = 0; break; }
        g_i64 = f;
    }
    int sp = t >> 6, c = t & 63;
    float a = 0.0f;
#pragma unroll 8
    for (int k = 0; k < kC; k++) a += Wemb[sp * kC + k] * Wx[k * kC + c];
    g_xfs[t] = a;
}

// ---------------- index conversion (nodes + edges in one grid) ----------------
__global__ void k_conv(const int* eraw, const int* braw, const int* spraw) {
    int i = blockIdx.x * blockDim.x + threadIdx.x;
    int f = g_i64;
    if (i < kN) {
        g_batch[i] = f ? braw[2 * i] : braw[i];
        g_sp[i]    = f ? spraw[2 * i] : spraw[i];
    }
    if (i < kE) {
        g_snd[i] = f ? eraw[2 * i]        : eraw[i];
        g_rcv[i] = f ? eraw[2 * (kE + i)] : eraw[kE + i];
    }
}

// ---------------- edge geometry ----------------
__global__ void k_geom(const float* __restrict__ pos,
                       const float* __restrict__ cell,
                       const float* __restrict__ Sij) {
    int e = blockIdx.x * blockDim.x + threadIdx.x;
    if (e >= kE) return;
    int snd = g_snd[e], rcv = g_rcv[e];
    int b = g_batch[snd];
    float s0 = Sij[e * 3 + 0], s1 = Sij[e * 3 + 1], s2 = Sij[e * 3 + 2];
    const float* cb = cell + b * 9;
    float sh0 = s0 * cb[0] + s1 * cb[3] + s2 * cb[6];
    float sh1 = s0 * cb[1] + s1 * cb[4] + s2 * cb[7];
    float sh2 = s0 * cb[2] + s1 * cb[5] + s2 * cb[8];
    const float invcut = 1.0f / 6.0f;
    float r0 = (pos[rcv * 3 + 0] - pos[snd * 3 + 0] + sh0) * invcut;
    float r1 = (pos[rcv * 3 + 1] - pos[snd * 3 + 1] + sh1) * invcut;
    float r2 = (pos[rcv * 3 + 2] - pos[snd * 3 + 2] + sh2) * invcut;
    float len = sqrtf(r0 * r0 + r1 * r1 + r2 * r2);
    float mask = (len > 0.0f) ? 1.0f : 0.0f;
    float safe = (len > 0.0f) ? len : 1.0f;
    float inv = 1.0f / safe;
    const float sq3 = 1.7320508075688772f;
    g_y1[e * 3 + 0] = sq3 * r0 * inv;
    g_y1[e * 3 + 1] = sq3 * r1 * inv;
    g_y1[e * 3 + 2] = sq3 * r2 * inv;
    float x = safe;
    float env = (x < 1.0f) ? (1.0f - 6.0f * x * x + 8.0f * x * x * x - 3.0f * x * x * x * x) : 0.0f;
    float fac = 1.4142135623730951f * inv * env * mask;
    const float pi = 3.14159265358979323846f;
#pragma unroll
    for (int nb = 1; nb <= kNB; nb++)
        g_ef[e * kNB + nb - 1] = fac * sinf(pi * (float)nb * safe);
    g_mask[e] = mask;
}

// ---------------- init: s, xf, zero v + agg ----------------
__global__ void k_init(const float* __restrict__ Wemb) {
    int t = blockIdx.x * blockDim.x + threadIdx.x;
    if (t >= kN * kC) return;
    int n = t / kC, c = t % kC;
    int sp = g_sp[n];
    g_s[t]  = Wemb[sp * kC + c];
    g_xf[t] = g_xfs[sp * kC + c];
    g_v[n * 192 + c * 3 + 0] = 0.0f;
    g_v[n * 192 + c * 3 + 1] = 0.0f;
    g_v[n * 192 + c * 3 + 2] = 0.0f;
    *(float4*)&g_agg[t * 4] = make_float4(0.f, 0.f, 0.f, 0.f);
}

// ---------------- up-projection ----------------
__global__ __launch_bounds__(256) void k_up(const float* __restrict__ Ws,
                                            const float* __restrict__ Wv) {
    __shared__ float sWs[4096], sWv[4096], ss[4][64], sv[4][192];
    int tid = threadIdx.x;
    for (int i = tid; i < 1024; i += 256) {
        ((float4*)sWs)[i] = ((const float4*)Ws)[i];
        ((float4*)sWv)[i] = ((const float4*)Wv)[i];
    }
    int slot = tid >> 6, o = tid & 63;
    int n = blockIdx.x * 4 + slot;
    ss[slot][o] = g_s[n * 64 + o];
    sv[slot][o * 3 + 0] = g_v[n * 192 + o * 3 + 0];
    sv[slot][o * 3 + 1] = g_v[n * 192 + o * 3 + 1];
    sv[slot][o * 3 + 2] = g_v[n * 192 + o * 3 + 2];
    __syncthreads();
    float su = 0.0f, v0 = 0.0f, v1 = 0.0f, v2 = 0.0f;
#pragma unroll 8
    for (int c = 0; c < 64; c++) {
        su += ss[slot][c] * sWs[c * 64 + o];
        float w = sWv[c * 64 + o];
        v0 += sv[slot][c * 3 + 0] * w;
        v1 += sv[slot][c * 3 + 1] * w;
        v2 += sv[slot][c * 3 + 2] * w;
    }
    *(float4*)&g_supv[n * 256 + o * 4] = make_float4(su, v0, v1, v2);
}

// ---------------- persistent edge kernel ----------------
// smem floats: Wr1 512 | br1 64 | br2 64 | Wr2 4096 | Wr3 16384
//              h1 TE*64 | h2 TE*64 | ef TE*8 | y TE*3 | msk TE | snd TE | rcv TE
constexpr int EDGE_SMEM = (512 + 64 + 64 + 4096 + 16384 +
                           TE * 64 + TE * 64 + TE * 8 + TE * 3 + TE + TE + TE) * 4;

__global__ __launch_bounds__(512, 1) void k_edge(const float* __restrict__ Wr1,
                                                 const float* __restrict__ br1,
                                                 const float* __restrict__ Wr2,
                                                 const float* __restrict__ br2,
                                                 const float* __restrict__ Wr3) {
    extern __shared__ float sm[];
    float* sWr1 = sm;                  // 512
    float* sbr1 = sWr1 + 512;          // 64
    float* sbr2 = sbr1 + 64;           // 64
    float* sWr2 = sbr2 + 64;           // 4096
    float* sWr3 = sWr2 + 4096;         // 16384
    float* sh1  = sWr3 + 16384;        // TE*64
    float* sh2  = sh1 + TE * 64;       // TE*64
    float* sef  = sh2 + TE * 64;       // TE*8
    float* sy   = sef + TE * 8;        // TE*3
    float* smk  = sy + TE * 3;         // TE
    int*   ssnd = (int*)(smk + TE);    // TE
    int*   srcv = ssnd + TE;           // TE

    int tid = threadIdx.x;
    // one-time weight staging (vectorized)
    for (int i = tid; i < 128; i += 512) ((float4*)sWr1)[i] = ((const float4*)Wr1)[i];
    if (tid < 64) { sbr1[tid] = br1[tid]; sbr2[tid] = br2[tid]; }
    for (int i = tid; i < 1024; i += 512) ((float4*)sWr2)[i] = ((const float4*)Wr2)[i];
    for (int i = tid; i < 4096; i += 512) ((float4*)sWr3)[i] = ((const float4*)Wr3)[i];

    int eg = tid >> 4;     // 0..31
    int cq = tid & 15;
    int c0 = cq * 4;
    int eb = eg * 4;

    const float inv_sqrt3 = 0.5773502691896258f;

    for (int tile = blockIdx.x; tile < NTILE; tile += EGRID) {
        int e0 = tile * TE;
        // ---- tile prologue: stage edge data ----
        for (int i = tid; i < TE * 8; i += 512) sef[i] = g_ef[e0 * 8 + i];
        for (int i = tid; i < TE * 3; i += 512) sy[i]  = g_y1[e0 * 3 + i];
        if (tid < TE) {
            smk[tid]  = g_mask[e0 + tid] * 0.03125f;   // fold 1/AVG
            ssnd[tid] = g_snd[e0 + tid];
            srcv[tid] = g_rcv[e0 + tid];
        }
        __syncthreads();

        // ---- h1 = silu(ef @ Wr1 + br1) ----
        {
            ull acc[4][2];
            ull b0 = pack2(sbr1[c0], sbr1[c0 + 1]);
            ull b1 = pack2(sbr1[c0 + 2], sbr1[c0 + 3]);
#pragma unroll
            for (int i = 0; i < 4; i++) { acc[i][0] = b0; acc[i][1] = b1; }
#pragma unroll
            for (int k = 0; k < 8; k++) {
                const ull* wp = (const ull*)&sWr1[k * 64 + c0];
                ull w0 = wp[0], w1 = wp[1];
#pragma unroll
                for (int i = 0; i < 4; i++) {
                    float h = sef[(eb + i) * 8 + k];
                    ull ha = pack2(h, h);
                    fma2(acc[i][0], ha, w0);
                    fma2(acc[i][1], ha, w1);
                }
            }
#pragma unroll
            for (int i = 0; i < 4; i++)
#pragma unroll
                for (int p = 0; p < 2; p++) {
                    float lo, hi; unpack2(acc[i][p], lo, hi);
                    sh1[(eb + i) * 64 + c0 + 2 * p]     = silu_f(lo);
                    sh1[(eb + i) * 64 + c0 + 2 * p + 1] = silu_f(hi);
                }
        }
        __syncthreads();

        // ---- h2 = silu(h1 @ Wr2 + br2) ----
        {
            ull acc[4][2];
            ull b0 = pack2(sbr2[c0], sbr2[c0 + 1]);
            ull b1 = pack2(sbr2[c0 + 2], sbr2[c0 + 3]);
#pragma unroll
            for (int i = 0; i < 4; i++) { acc[i][0] = b0; acc[i][1] = b1; }
#pragma unroll 4
            for (int k = 0; k < 64; k++) {
                const ull* wp = (const ull*)&sWr2[k * 64 + c0];
                ull w0 = wp[0], w1 = wp[1];
#pragma unroll
                for (int i = 0; i < 4; i++) {
                    float h = sh1[(eb + i) * 64 + k];
                    ull ha = pack2(h, h);
                    fma2(acc[i][0], ha, w0);
                    fma2(acc[i][1], ha, w1);
                }
            }
#pragma unroll
            for (int i = 0; i < 4; i++)
#pragma unroll
                for (int p = 0; p < 2; p++) {
                    float lo, hi; unpack2(acc[i][p], lo, hi);
                    sh2[(eb + i) * 64 + c0 + 2 * p]     = silu_f(lo);
                    sh2[(eb + i) * 64 + c0 + 2 * p + 1] = silu_f(hi);
                }
        }
        __syncthreads();

        // ---- wts = h2 @ Wr3, fused with messages + scatter ----
        ull acc3[4][4][2];
#pragma unroll
        for (int i = 0; i < 4; i++)
#pragma unroll
            for (int t = 0; t < 4; t++) { acc3[i][t][0] = 0ULL; acc3[i][t][1] = 0ULL; }

#pragma unroll 2
        for (int k = 0; k < 64; k++) {
            ull ha[4];
#pragma unroll
            for (int i = 0; i < 4; i++) {
                float h = sh2[(eb + i) * 64 + k];
                ha[i] = pack2(h, h);
            }
            const ull* wr = (const ull*)&sWr3[k * 256 + c0];
#pragma unroll
            for (int t = 0; t < 4; t++) {
                ull w0 = wr[t * 32], w1 = wr[t * 32 + 1];
#pragma unroll
                for (int i = 0; i < 4; i++) {
                    fma2(acc3[i][t][0], ha[i], w0);
                    fma2(acc3[i][t][1], ha[i], w1);
                }
            }
        }

#pragma unroll
        for (int i = 0; i < 4; i++) {
            int le = eb + i;
            float msk = smk[le];
            float y0 = sy[le * 3 + 0], y1v = sy[le * 3 + 1], y2 = sy[le * 3 + 2];
            int snd = ssnd[le], rcv = srcv[le];
            const float4* svp = (const float4*)&g_supv[snd * 256];
            float* agp = &g_agg[rcv * 256];
            float4 sv[4];
#pragma unroll
            for (int q = 0; q < 4; q++) sv[q] = svp[c0 + q];
#pragma unroll
            for (int p = 0; p < 2; p++) {
                float wt[4][2];
#pragma unroll
                for (int t = 0; t < 4; t++) unpack2(acc3[i][t][p], wt[t][0], wt[t][1]);
#pragma unroll
                for (int jj = 0; jj < 2; jj++) {
                    int q = 2 * p + jj;
                    int c = c0 + q;
                    float w0 = wt[0][jj] * msk, w1 = wt[1][jj] * msk;
                    float w2 = wt[2][jj] * msk, w3 = wt[3][jj] * msk;
                    float4 s4 = sv[q];
                    float dot = (s4.y * y0 + s4.z * y1v + s4.w * y2) * inv_sqrt3;
                    float ms  = w0 * s4.x + w1 * dot;
                    float a0  = w2 * s4.x;
                    red4(agp + c * 4,
                         ms,
                         a0 * y0  + w3 * s4.y,
                         a0 * y1v + w3 * s4.z,
                         a0 * y2  + w3 * s4.w);
                }
            }
        }
        __syncthreads();   // protect sh2/sef before next tile overwrites
    }
}

// ---------------- node update (also zeroes g_agg for next layer) ----------------
constexpr int NODE_SMEM = (4 * 4096 + 1024 + 256 + 768 + 256 + 768 + 768) * 4;

__global__ __launch_bounds__(256) void k_node(const float* __restrict__ Wms,
                                              const float* __restrict__ Wmv,
                                              const float* __restrict__ Wscs,
                                              const float* __restrict__ Wscv,
                                              const float* __restrict__ Wps,
                                              const float* __restrict__ Wpv,
                                              const float* __restrict__ Wread, int l) {
    extern __shared__ float sm[];
    float* sWms = sm;
    float* sWmv = sWms + 4096;
    float* sWps = sWmv + 4096;
    float* sWpv = sWps + 4096;
    float* sagg = sWpv + 4096;   // [4][64][4]
    float* sold = sagg + 1024;
    float* vold = sold + 256;
    float* sts  = vold + 768;
    float* stv  = sts + 256;
    float* vnew = stv + 768;

    int tid = threadIdx.x;
    for (int i = tid; i < 1024; i += 256) {
        ((float4*)sWms)[i] = ((const float4*)Wms)[i];
        ((float4*)sWmv)[i] = ((const float4*)Wmv)[i];
        ((float4*)sWps)[i] = ((const float4*)Wps)[i];
        ((float4*)sWpv)[i] = ((const float4*)Wpv)[i];
    }
    int slot = tid >> 6, o = tid & 63;
    int n = blockIdx.x * 4 + slot;
    *(float4*)&sagg[slot * 256 + o * 4] = *(const float4*)&g_agg[n * 256 + o * 4];
    *(float4*)&g_agg[n * 256 + o * 4] = make_float4(0.f, 0.f, 0.f, 0.f); // zero for next layer
    sold[slot * 64 + o] = g_s[n * 64 + o];
    vold[slot * 192 + o * 3 + 0] = g_v[n * 192 + o * 3 + 0];
    vold[slot * 192 + o * 3 + 1] = g_v[n * 192 + o * 3 + 1];
    vold[slot * 192 + o * 3 + 2] = g_v[n * 192 + o * 3 + 2];
    __syncthreads();

    int sp = g_sp[n];
    const float* Wss = Wscs + sp * 4096;
    const float* Wsv = Wscv + sp * 4096;

    float ms = 0, mv0 = 0, mv1 = 0, mv2 = 0;
    float scs = 0, scv0 = 0, scv1 = 0, scv2 = 0;
#pragma unroll 4
    for (int c = 0; c < 64; c++) {
        const float* ag = &sagg[slot * 256 + c * 4];
        ms  += ag[0] * sWms[c * 64 + o];
        float wm = sWmv[c * 64 + o];
        mv0 += ag[1] * wm; mv1 += ag[2] * wm; mv2 += ag[3] * wm;
        scs += sold[slot * 64 + c] * Wss[c * 64 + o];
        float wv = Wsv[c * 64 + o];
        scv0 += vold[slot * 192 + c * 3 + 0] * wv;
        scv1 += vold[slot * 192 + c * 3 + 1] * wv;
        scv2 += vold[slot * 192 + c * 3 + 2] * wv;
    }
    float xfo = g_xf[n * 64 + o];
    sts[slot * 64 + o] = xfo * ms;
    stv[slot * 192 + o * 3 + 0] = xfo * mv0;
    stv[slot * 192 + o * 3 + 1] = xfo * mv1;
    stv[slot * 192 + o * 3 + 2] = xfo * mv2;
    __syncthreads();

    float sn = scs, vn0 = scv0, vn1 = scv1, vn2 = scv2;
#pragma unroll 4
    for (int c = 0; c < 64; c++) {
        sn += sts[slot * 64 + c] * sWps[c * 64 + o];
        float wp = sWpv[c * 64 + o];
        vn0 += stv[slot * 192 + c * 3 + 0] * wp;
        vn1 += stv[slot * 192 + c * 3 + 1] * wp;
        vn2 += stv[slot * 192 + c * 3 + 2] * wp;
    }
    g_s[n * 64 + o] = sn;
    g_v[n * 192 + o * 3 + 0] = vn0;
    g_v[n * 192 + o * 3 + 1] = vn1;
    g_v[n * 192 + o * 3 + 2] = vn2;
    vnew[slot * 192 + o * 3 + 0] = vn0;
    vnew[slot * 192 + o * 3 + 1] = vn1;
    vnew[slot * 192 + o * 3 + 2] = vn2;
    __syncthreads();

    if (o < 9) {
        int ro = o / 3, m = o % 3;
        float a = 0.0f;
#pragma unroll 8
        for (int c = 0; c < 64; c++) a += vnew[slot * 192 + c * 3 + m] * Wread[ro * 64 + c];
        g_outs[l * kN * 9 + n * 9 + o] = a;
    }
}

// ---------------- final reduce ----------------
__global__ void k_final(float* __restrict__ out) {
    __shared__ float acc[72];
    int tid = threadIdx.x;
    if (tid < 72) acc[tid] = 0.0f;
    __syncthreads();
    int n = blockIdx.x * blockDim.x + tid;
    if (n < kN) {
        int b = g_batch[n];
#pragma unroll
        for (int j = 0; j < 9; j++) {
            float x = 0.0f;
#pragma unroll
            for (int l = 0; l < kL; l++) x += silu_f(g_outs[l * kN * 9 + n * 9 + j]);
            atomicAdd(&acc[b * 9 + j], x);
        }
    }
    __syncthreads();
    if (tid < 72) atomicAdd(&out[tid], acc[tid]);
}

// ---------------- launch ----------------
extern "C" void kernel_launch(void* const* d_in, const int* in_sizes, int n_in,
                              void* d_out, int out_size) {
    const float* pos  = (const float*)d_in[0];
    const float* cell = (const float*)d_in[1];
    const float* Sij  = (const float*)d_in[2];
    const float* Wemb = (const float*)d_in[3];
    const float* Wx   = (const float*)d_in[4];
    const float* Wups = (const float*)d_in[5];
    const float* Wupv = (const float*)d_in[6];
    const float* Wr1  = (const float*)d_in[7];
    const float* br1  = (const float*)d_in[8];
    const float* Wr2  = (const float*)d_in[9];
    const float* br2  = (const float*)d_in[10];
    const float* Wr3  = (const float*)d_in[11];
    const float* Wms  = (const float*)d_in[12];
    const float* Wmv  = (const float*)d_in[13];
    const float* Wscs = (const float*)d_in[14];
    const float* Wscv = (const float*)d_in[15];
    const float* Wps  = (const float*)d_in[16];
    const float* Wpv  = (const float*)d_in[17];
    const float* Wread= (const float*)d_in[18];
    const int* ei     = (const int*)d_in[19];
    const int* braw   = (const int*)d_in[20];
    const int* spraw  = (const int*)d_in[21];
    float* out = (float*)d_out;

    cudaFuncSetAttribute(k_edge, cudaFuncAttributeMaxDynamicSharedMemorySize, EDGE_SMEM);
    cudaFuncSetAttribute(k_node, cudaFuncAttributeMaxDynamicSharedMemorySize, NODE_SMEM);

    k_detect_spec<<<1, 512>>>(spraw, Wemb, Wx);
    k_conv<<<(kE + 255) / 256, 256>>>(ei, braw, spraw);
    k_geom<<<(kE + 255) / 256, 256>>>(pos, cell, Sij);
    k_init<<<(kN * kC + 255) / 256, 256>>>(Wemb);
    cudaMemsetAsync(out, 0, 72 * sizeof(float));

    for (int l = 0; l < kL; l++) {
        k_up<<<kN / 4, 256>>>(Wups + l * 4096, Wupv + l * 4096);
        k_edge<<<EGRID, 512, EDGE_SMEM>>>(Wr1 + l * 512, br1 + l * 64,
                                          Wr2 + l * 4096, br2 + l * 64,
                                          Wr3 + l * 16384);
        k_node<<<kN / 4, 256, NODE_SMEM>>>(Wms + l * 4096, Wmv + l * 4096,
                                           Wscs + l * 32768, Wscv + l * 32768,
                                           Wps + l * 4096, Wpv + l * 4096,
                                           Wread + l * 192, l);
    }
    k_final<<<(kN + 255) / 256, 256>>>(out);
}

// round 4
// speedup vs baseline: 3.1388x; 1.0661x over previous
#include <cuda_runtime.h>
#include <math.h>

constexpr int kN  = 20000;
constexpr int kG  = 8;
constexpr int kE  = 640000;
constexpr int kC  = 64;
constexpr int kNB = 8;
constexpr int kL  = 3;
constexpr int TE  = 128;
constexpr int NTILE = kE / TE;
constexpr int EGRID = 152;

// ---------------- device scratch ----------------
__device__ float g_ef[kE * kNB];      // permuted order
__device__ float g_y1[kE * 3];        // permuted order
__device__ float g_mask[kE];          // permuted order
__device__ int   g_snd[kE];           // original order
__device__ int   g_rcv[kE];           // original order
__device__ int   g_psnd[kE];          // permuted
__device__ int   g_prcv[kE];          // permuted
__device__ int   g_pe[kE];            // perm: pos -> original edge
__device__ int   g_slot[kE];
__device__ int   g_cnt[kN];
__device__ int   g_base[kN];
__device__ int   g_sp[kN];
__device__ int   g_batch[kN];
__device__ float g_s[kN * kC];
__device__ float g_xf[kN * kC];
__device__ float g_xfs[8 * kC];
__device__ float g_sup0[8 * kC];      // layer-0 per-species s_up
__device__ float g_v[kN * kC * 3];
__device__ float g_supv[kN * kC * 4];
__device__ float g_agg[kN * kC * 4];
__device__ float g_outs[kL * kN * 9];
__device__ int   g_i64;

typedef unsigned long long ull;

__device__ __forceinline__ float silu_f(float x) {
    return __fdividef(x, 1.0f + __expf(-x));
}
__device__ __forceinline__ ull pack2(float lo, float hi) {
    ull r; asm("mov.b64 %0,{%1,%2};" : "=l"(r) : "f"(lo), "f"(hi)); return r;
}
__device__ __forceinline__ void unpack2(ull v, float& lo, float& hi) {
    asm("mov.b64 {%0,%1},%2;" : "=f"(lo), "=f"(hi) : "l"(v));
}
__device__ __forceinline__ void fma2(ull& d, ull a, ull b) {
    asm("fma.rn.f32x2 %0,%1,%2,%0;" : "+l"(d) : "l"(a), "l"(b));
}
__device__ __forceinline__ void red4(float* p, float a, float b, float c, float d) {
    asm volatile("red.global.add.v4.f32 [%0],{%1,%2,%3,%4};"
                 :: "l"(p), "f"(a), "f"(b), "f"(c), "f"(d) : "memory");
}

// ---- launch 1: detect int width, per-species tables, zero counts ----
__global__ void k_detect_spec(const int* sp_raw, const float* __restrict__ Wemb,
                              const float* __restrict__ Wx,
                              const float* __restrict__ Wups0) {
    int i = blockIdx.x * blockDim.x + threadIdx.x;
    if (i < kN) g_cnt[i] = 0;
    if (blockIdx.x == 0) {
        int t = threadIdx.x;
        if (t == 0) {
            int f = 1;
            for (int k = 0; k < 128; k++)
                if (sp_raw[2 * k + 1] != 0) { f = 0; break; }
            g_i64 = f;
        }
#pragma unroll
        for (int r = 0; r < 2; r++) {
            int u = t + 256 * r;         // 0..511
            int sp = u >> 6, c = u & 63;
            float a = 0.0f, b = 0.0f;
#pragma unroll 8
            for (int k = 0; k < kC; k++) {
                float w = Wemb[sp * kC + k];
                a += w * Wx[k * kC + c];
                b += w * Wups0[k * kC + c];
            }
            g_xfs[u]  = a;
            g_sup0[u] = b;
        }
    }
}

// ---- launch 2: index conversion + degree count ----
__global__ void k_conv(const int* eraw, const int* braw, const int* spraw) {
    int i = blockIdx.x * blockDim.x + threadIdx.x;
    int f = g_i64;
    if (i < kN) {
        g_batch[i] = f ? braw[2 * i] : braw[i];
        g_sp[i]    = f ? spraw[2 * i] : spraw[i];
    }
    if (i < kE) {
        int snd = f ? eraw[2 * i]        : eraw[i];
        int rcv = f ? eraw[2 * (kE + i)] : eraw[kE + i];
        g_snd[i] = snd;
        g_rcv[i] = rcv;
        g_slot[i] = atomicAdd(&g_cnt[rcv], 1);
    }
}

// ---- launch 3: single-block exclusive scan of counts; zero d_out ----
__global__ void k_scan(float* __restrict__ out) {
    __shared__ int buf[1024];
    __shared__ int carry;
    int tid = threadIdx.x;
    if (tid < 72) out[tid] = 0.0f;
    if (tid == 0) carry = 0;
    __syncthreads();
    for (int base = 0; base < kN; base += 1024) {
        int i = base + tid;
        int v = (i < kN) ? g_cnt[i] : 0;
        buf[tid] = v;
        __syncthreads();
        for (int off = 1; off < 1024; off <<= 1) {
            int t = (tid >= off) ? buf[tid - off] : 0;
            __syncthreads();
            buf[tid] += t;
            __syncthreads();
        }
        if (i < kN) g_base[i] = carry + buf[tid] - v;
        __syncthreads();
        if (tid == 1023) carry += buf[1023];
        __syncthreads();
    }
}

// ---- launch 4: build permutation + node init (fused) ----
__global__ void k_perm_init(const float* __restrict__ Wemb) {
    int t = blockIdx.x * blockDim.x + threadIdx.x;
    if (t < kE) {
        int rcv = g_rcv[t];
        g_pe[g_base[rcv] + g_slot[t]] = t;
    }
    if (t < kN * kC) {
        int n = t / kC, c = t % kC;
        int sp = g_sp[n];
        g_s[t]  = Wemb[sp * kC + c];
        g_xf[t] = g_xfs[sp * kC + c];
        g_v[n * 192 + c * 3 + 0] = 0.0f;
        g_v[n * 192 + c * 3 + 1] = 0.0f;
        g_v[n * 192 + c * 3 + 2] = 0.0f;
        *(float4*)&g_agg[t * 4] = make_float4(0.f, 0.f, 0.f, 0.f);
        // layer-0 supv: s_up per-species, v_up = 0
        *(float4*)&g_supv[t * 4] = make_float4(g_sup0[sp * kC + c], 0.f, 0.f, 0.f);
    }
}

// ---- launch 5: geometry in permuted order ----
__global__ void k_geom(const float* __restrict__ pos,
                       const float* __restrict__ cell,
                       const float* __restrict__ Sij) {
    int p = blockIdx.x * blockDim.x + threadIdx.x;
    if (p >= kE) return;
    int e = g_pe[p];
    int snd = g_snd[e], rcv = g_rcv[e];
    g_psnd[p] = snd;
    g_prcv[p] = rcv;
    int b = g_batch[snd];
    float s0 = Sij[e * 3 + 0], s1 = Sij[e * 3 + 1], s2 = Sij[e * 3 + 2];
    const float* cb = cell + b * 9;
    float sh0 = s0 * cb[0] + s1 * cb[3] + s2 * cb[6];
    float sh1 = s0 * cb[1] + s1 * cb[4] + s2 * cb[7];
    float sh2 = s0 * cb[2] + s1 * cb[5] + s2 * cb[8];
    const float invcut = 1.0f / 6.0f;
    float r0 = (pos[rcv * 3 + 0] - pos[snd * 3 + 0] + sh0) * invcut;
    float r1 = (pos[rcv * 3 + 1] - pos[snd * 3 + 1] + sh1) * invcut;
    float r2 = (pos[rcv * 3 + 2] - pos[snd * 3 + 2] + sh2) * invcut;
    float len = sqrtf(r0 * r0 + r1 * r1 + r2 * r2);
    float mask = (len > 0.0f) ? 1.0f : 0.0f;
    float safe = (len > 0.0f) ? len : 1.0f;
    float inv = 1.0f / safe;
    const float sq3 = 1.7320508075688772f;
    g_y1[p * 3 + 0] = sq3 * r0 * inv;
    g_y1[p * 3 + 1] = sq3 * r1 * inv;
    g_y1[p * 3 + 2] = sq3 * r2 * inv;
    float x = safe;
    float env = (x < 1.0f) ? (1.0f - 6.0f * x * x + 8.0f * x * x * x - 3.0f * x * x * x * x) : 0.0f;
    float fac = 1.4142135623730951f * inv * env * mask;
    const float pi = 3.14159265358979323846f;
#pragma unroll
    for (int nb = 1; nb <= kNB; nb++)
        g_ef[p * kNB + nb - 1] = fac * sinf(pi * (float)nb * safe);
    g_mask[p] = mask;
}

// ---- up-projection (layers 1,2 only) ----
__global__ __launch_bounds__(256) void k_up(const float* __restrict__ Ws,
                                            const float* __restrict__ Wv) {
    __shared__ float sWs[4096], sWv[4096], ss[4][64], sv[4][192];
    int tid = threadIdx.x;
    for (int i = tid; i < 1024; i += 256) {
        ((float4*)sWs)[i] = ((const float4*)Ws)[i];
        ((float4*)sWv)[i] = ((const float4*)Wv)[i];
    }
    int slot = tid >> 6, o = tid & 63;
    int n = blockIdx.x * 4 + slot;
    ss[slot][o] = g_s[n * 64 + o];
    sv[slot][o * 3 + 0] = g_v[n * 192 + o * 3 + 0];
    sv[slot][o * 3 + 1] = g_v[n * 192 + o * 3 + 1];
    sv[slot][o * 3 + 2] = g_v[n * 192 + o * 3 + 2];
    __syncthreads();
    float su = 0.0f, v0 = 0.0f, v1 = 0.0f, v2 = 0.0f;
#pragma unroll 8
    for (int c = 0; c < 64; c++) {
        su += ss[slot][c] * sWs[c * 64 + o];
        float w = sWv[c * 64 + o];
        v0 += sv[slot][c * 3 + 0] * w;
        v1 += sv[slot][c * 3 + 1] * w;
        v2 += sv[slot][c * 3 + 2] * w;
    }
    *(float4*)&g_supv[n * 256 + o * 4] = make_float4(su, v0, v1, v2);
}

// ---- persistent edge kernel (rcv-sorted, register-merged scatter) ----
constexpr int EDGE_SMEM = (512 + 64 + 64 + 4096 + 16384 +
                           TE * 64 + TE * 64 + TE * 8 + TE * 3 + TE + TE + TE) * 4;

__global__ __launch_bounds__(512, 1) void k_edge(const float* __restrict__ Wr1,
                                                 const float* __restrict__ br1,
                                                 const float* __restrict__ Wr2,
                                                 const float* __restrict__ br2,
                                                 const float* __restrict__ Wr3) {
    extern __shared__ float sm[];
    float* sWr1 = sm;
    float* sbr1 = sWr1 + 512;
    float* sbr2 = sbr1 + 64;
    float* sWr2 = sbr2 + 64;
    float* sWr3 = sWr2 + 4096;
    float* sh1  = sWr3 + 16384;
    float* sh2  = sh1 + TE * 64;
    float* sef  = sh2 + TE * 64;
    float* sy   = sef + TE * 8;
    float* smk  = sy + TE * 3;
    int*   ssnd = (int*)(smk + TE);
    int*   srcv = ssnd + TE;

    int tid = threadIdx.x;
    for (int i = tid; i < 128; i += 512) ((float4*)sWr1)[i] = ((const float4*)Wr1)[i];
    if (tid < 64) { sbr1[tid] = br1[tid]; sbr2[tid] = br2[tid]; }
    for (int i = tid; i < 1024; i += 512) ((float4*)sWr2)[i] = ((const float4*)Wr2)[i];
    for (int i = tid; i < 4096; i += 512) ((float4*)sWr3)[i] = ((const float4*)Wr3)[i];

    int eg = tid >> 4;
    int cq = tid & 15;
    int c0 = cq * 4;
    int eb = eg * 4;

    const float inv_sqrt3 = 0.5773502691896258f;

    for (int tile = blockIdx.x; tile < NTILE; tile += EGRID) {
        int e0 = tile * TE;
        for (int i = tid; i < TE * 8; i += 512) sef[i] = g_ef[e0 * 8 + i];
        for (int i = tid; i < TE * 3; i += 512) sy[i]  = g_y1[e0 * 3 + i];
        if (tid < TE) {
            smk[tid]  = g_mask[e0 + tid] * 0.03125f;
            ssnd[tid] = g_psnd[e0 + tid];
            srcv[tid] = g_prcv[e0 + tid];
        }
        __syncthreads();

        // h1
        {
            ull acc[4][2];
            ull b0 = pack2(sbr1[c0], sbr1[c0 + 1]);
            ull b1 = pack2(sbr1[c0 + 2], sbr1[c0 + 3]);
#pragma unroll
            for (int i = 0; i < 4; i++) { acc[i][0] = b0; acc[i][1] = b1; }
#pragma unroll
            for (int k = 0; k < 8; k++) {
                const ull* wp = (const ull*)&sWr1[k * 64 + c0];
                ull w0 = wp[0], w1 = wp[1];
#pragma unroll
                for (int i = 0; i < 4; i++) {
                    float h = sef[(eb + i) * 8 + k];
                    ull ha = pack2(h, h);
                    fma2(acc[i][0], ha, w0);
                    fma2(acc[i][1], ha, w1);
                }
            }
#pragma unroll
            for (int i = 0; i < 4; i++)
#pragma unroll
                for (int p = 0; p < 2; p++) {
                    float lo, hi; unpack2(acc[i][p], lo, hi);
                    sh1[(eb + i) * 64 + c0 + 2 * p]     = silu_f(lo);
                    sh1[(eb + i) * 64 + c0 + 2 * p + 1] = silu_f(hi);
                }
        }
        __syncthreads();

        // h2
        {
            ull acc[4][2];
            ull b0 = pack2(sbr2[c0], sbr2[c0 + 1]);
            ull b1 = pack2(sbr2[c0 + 2], sbr2[c0 + 3]);
#pragma unroll
            for (int i = 0; i < 4; i++) { acc[i][0] = b0; acc[i][1] = b1; }
#pragma unroll 4
            for (int k = 0; k < 64; k++) {
                const ull* wp = (const ull*)&sWr2[k * 64 + c0];
                ull w0 = wp[0], w1 = wp[1];
#pragma unroll
                for (int i = 0; i < 4; i++) {
                    float h = sh1[(eb + i) * 64 + k];
                    ull ha = pack2(h, h);
                    fma2(acc[i][0], ha, w0);
                    fma2(acc[i][1], ha, w1);
                }
            }
#pragma unroll
            for (int i = 0; i < 4; i++)
#pragma unroll
                for (int p = 0; p < 2; p++) {
                    float lo, hi; unpack2(acc[i][p], lo, hi);
                    sh2[(eb + i) * 64 + c0 + 2 * p]     = silu_f(lo);
                    sh2[(eb + i) * 64 + c0 + 2 * p + 1] = silu_f(hi);
                }
        }
        __syncthreads();

        // wts GEMM
        ull acc3[4][4][2];
#pragma unroll
        for (int i = 0; i < 4; i++)
#pragma unroll
            for (int t = 0; t < 4; t++) { acc3[i][t][0] = 0ULL; acc3[i][t][1] = 0ULL; }

#pragma unroll 2
        for (int k = 0; k < 64; k++) {
            ull ha[4];
#pragma unroll
            for (int i = 0; i < 4; i++) {
                float h = sh2[(eb + i) * 64 + k];
                ha[i] = pack2(h, h);
            }
            const ull* wr = (const ull*)&sWr3[k * 256 + c0];
#pragma unroll
            for (int t = 0; t < 4; t++) {
                ull w0 = wr[t * 32], w1 = wr[t * 32 + 1];
#pragma unroll
                for (int i = 0; i < 4; i++) {
                    fma2(acc3[i][t][0], ha[i], w0);
                    fma2(acc3[i][t][1], ha[i], w1);
                }
            }
        }

        // messages with register-merged scatter (edges sorted by rcv)
        {
            int cur = -1;
            float aq[4][4];
#pragma unroll
            for (int i = 0; i < 4; i++) {
                int le = eb + i;
                int rcv = srcv[le];
                if (rcv != cur) {
                    if (cur >= 0) {
                        float* agp = &g_agg[cur * 256];
#pragma unroll
                        for (int q = 0; q < 4; q++)
                            red4(agp + (c0 + q) * 4, aq[q][0], aq[q][1], aq[q][2], aq[q][3]);
                    }
                    cur = rcv;
#pragma unroll
                    for (int q = 0; q < 4; q++)
                        aq[q][0] = aq[q][1] = aq[q][2] = aq[q][3] = 0.0f;
                }
                float msk = smk[le];
                float y0 = sy[le * 3 + 0], y1v = sy[le * 3 + 1], y2 = sy[le * 3 + 2];
                int snd = ssnd[le];
                const float4* svp = (const float4*)&g_supv[snd * 256];
#pragma unroll
                for (int p = 0; p < 2; p++) {
                    float wt[4][2];
#pragma unroll
                    for (int t = 0; t < 4; t++) unpack2(acc3[i][t][p], wt[t][0], wt[t][1]);
#pragma unroll
                    for (int jj = 0; jj < 2; jj++) {
                        int q = 2 * p + jj;
                        float w0 = wt[0][jj] * msk, w1 = wt[1][jj] * msk;
                        float w2 = wt[2][jj] * msk, w3 = wt[3][jj] * msk;
                        float4 s4 = svp[c0 + q];
                        float dot = (s4.y * y0 + s4.z * y1v + s4.w * y2) * inv_sqrt3;
                        float a0 = w2 * s4.x;
                        aq[q][0] += w0 * s4.x + w1 * dot;
                        aq[q][1] += a0 * y0  + w3 * s4.y;
                        aq[q][2] += a0 * y1v + w3 * s4.z;
                        aq[q][3] += a0 * y2  + w3 * s4.w;
                    }
                }
            }
            if (cur >= 0) {
                float* agp = &g_agg[cur * 256];
#pragma unroll
                for (int q = 0; q < 4; q++)
                    red4(agp + (c0 + q) * 4, aq[q][0], aq[q][1], aq[q][2], aq[q][3]);
            }
        }
        __syncthreads();
    }
}

// ---- node update (zeroes g_agg for next layer) ----
constexpr int NODE_SMEM = (4 * 4096 + 1024 + 256 + 768 + 256 + 768 + 768) * 4;

__global__ __launch_bounds__(256) void k_node(const float* __restrict__ Wms,
                                              const float* __restrict__ Wmv,
                                              const float* __restrict__ Wscs,
                                              const float* __restrict__ Wscv,
                                              const float* __restrict__ Wps,
                                              const float* __restrict__ Wpv,
                                              const float* __restrict__ Wread, int l) {
    extern __shared__ float sm[];
    float* sWms = sm;
    float* sWmv = sWms + 4096;
    float* sWps = sWmv + 4096;
    float* sWpv = sWps + 4096;
    float* sagg = sWpv + 4096;
    float* sold = sagg + 1024;
    float* vold = sold + 256;
    float* sts  = vold + 768;
    float* stv  = sts + 256;
    float* vnew = stv + 768;

    int tid = threadIdx.x;
    for (int i = tid; i < 1024; i += 256) {
        ((float4*)sWms)[i] = ((const float4*)Wms)[i];
        ((float4*)sWmv)[i] = ((const float4*)Wmv)[i];
        ((float4*)sWps)[i] = ((const float4*)Wps)[i];
        ((float4*)sWpv)[i] = ((const float4*)Wpv)[i];
    }
    int slot = tid >> 6, o = tid & 63;
    int n = blockIdx.x * 4 + slot;
    *(float4*)&sagg[slot * 256 + o * 4] = *(const float4*)&g_agg[n * 256 + o * 4];
    *(float4*)&g_agg[n * 256 + o * 4] = make_float4(0.f, 0.f, 0.f, 0.f);
    sold[slot * 64 + o] = g_s[n * 64 + o];
    vold[slot * 192 + o * 3 + 0] = g_v[n * 192 + o * 3 + 0];
    vold[slot * 192 + o * 3 + 1] = g_v[n * 192 + o * 3 + 1];
    vold[slot * 192 + o * 3 + 2] = g_v[n * 192 + o * 3 + 2];
    __syncthreads();

    int sp = g_sp[n];
    const float* Wss = Wscs + sp * 4096;
    const float* Wsv = Wscv + sp * 4096;

    float ms = 0, mv0 = 0, mv1 = 0, mv2 = 0;
    float scs = 0, scv0 = 0, scv1 = 0, scv2 = 0;
#pragma unroll 4
    for (int c = 0; c < 64; c++) {
        const float* ag = &sagg[slot * 256 + c * 4];
        ms  += ag[0] * sWms[c * 64 + o];
        float wm = sWmv[c * 64 + o];
        mv0 += ag[1] * wm; mv1 += ag[2] * wm; mv2 += ag[3] * wm;
        scs += sold[slot * 64 + c] * Wss[c * 64 + o];
        float wv = Wsv[c * 64 + o];
        scv0 += vold[slot * 192 + c * 3 + 0] * wv;
        scv1 += vold[slot * 192 + c * 3 + 1] * wv;
        scv2 += vold[slot * 192 + c * 3 + 2] * wv;
    }
    float xfo = g_xf[n * 64 + o];
    sts[slot * 64 + o] = xfo * ms;
    stv[slot * 192 + o * 3 + 0] = xfo * mv0;
    stv[slot * 192 + o * 3 + 1] = xfo * mv1;
    stv[slot * 192 + o * 3 + 2] = xfo * mv2;
    __syncthreads();

    float sn = scs, vn0 = scv0, vn1 = scv1, vn2 = scv2;
#pragma unroll 4
    for (int c = 0; c < 64; c++) {
        sn += sts[slot * 64 + c] * sWps[c * 64 + o];
        float wp = sWpv[c * 64 + o];
        vn0 += stv[slot * 192 + c * 3 + 0] * wp;
        vn1 += stv[slot * 192 + c * 3 + 1] * wp;
        vn2 += stv[slot * 192 + c * 3 + 2] * wp;
    }
    g_s[n * 64 + o] = sn;
    g_v[n * 192 + o * 3 + 0] = vn0;
    g_v[n * 192 + o * 3 + 1] = vn1;
    g_v[n * 192 + o * 3 + 2] = vn2;
    vnew[slot * 192 + o * 3 + 0] = vn0;
    vnew[slot * 192 + o * 3 + 1] = vn1;
    vnew[slot * 192 + o * 3 + 2] = vn2;
    __syncthreads();

    if (o < 9) {
        int ro = o / 3, m = o % 3;
        float a = 0.0f;
#pragma unroll 8
        for (int c = 0; c < 64; c++) a += vnew[slot * 192 + c * 3 + m] * Wread[ro * 64 + c];
        g_outs[l * kN * 9 + n * 9 + o] = a;
    }
}

// ---- final reduce ----
__global__ void k_final(float* __restrict__ out) {
    __shared__ float acc[72];
    int tid = threadIdx.x;
    if (tid < 72) acc[tid] = 0.0f;
    __syncthreads();
    int n = blockIdx.x * blockDim.x + tid;
    if (n < kN) {
        int b = g_batch[n];
#pragma unroll
        for (int j = 0; j < 9; j++) {
            float x = 0.0f;
#pragma unroll
            for (int l = 0; l < kL; l++) x += silu_f(g_outs[l * kN * 9 + n * 9 + j]);
            atomicAdd(&acc[b * 9 + j], x);
        }
    }
    __syncthreads();
    if (tid < 72) atomicAdd(&out[tid], acc[tid]);
}

// ---- launch ----
extern "C" void kernel_launch(void* const* d_in, const int* in_sizes, int n_in,
                              void* d_out, int out_size) {
    const float* pos  = (const float*)d_in[0];
    const float* cell = (const float*)d_in[1];
    const float* Sij  = (const float*)d_in[2];
    const float* Wemb = (const float*)d_in[3];
    const float* Wx   = (const float*)d_in[4];
    const float* Wups = (const float*)d_in[5];
    const float* Wupv = (const float*)d_in[6];
    const float* Wr1  = (const float*)d_in[7];
    const float* br1  = (const float*)d_in[8];
    const float* Wr2  = (const float*)d_in[9];
    const float* br2  = (const float*)d_in[10];
    const float* Wr3  = (const float*)d_in[11];
    const float* Wms  = (const float*)d_in[12];
    const float* Wmv  = (const float*)d_in[13];
    const float* Wscs = (const float*)d_in[14];
    const float* Wscv = (const float*)d_in[15];
    const float* Wps  = (const float*)d_in[16];
    const float* Wpv  = (const float*)d_in[17];
    const float* Wread= (const float*)d_in[18];
    const int* ei     = (const int*)d_in[19];
    const int* braw   = (const int*)d_in[20];
    const int* spraw  = (const int*)d_in[21];
    float* out = (float*)d_out;

    cudaFuncSetAttribute(k_edge, cudaFuncAttributeMaxDynamicSharedMemorySize, EDGE_SMEM);
    cudaFuncSetAttribute(k_node, cudaFuncAttributeMaxDynamicSharedMemorySize, NODE_SMEM);

    k_detect_spec<<<(kN + 255) / 256, 256>>>(spraw, Wemb, Wx, Wups);   // 1
    k_conv<<<(kE + 255) / 256, 256>>>(ei, braw, spraw);                // 2
    k_scan<<<1, 1024>>>(out);                                          // 3
    k_perm_init<<<(kN * kC + 255) / 256, 256>>>(Wemb);                 // 4
    k_geom<<<(kE + 255) / 256, 256>>>(pos, cell, Sij);                 // 5

    for (int l = 0; l < kL; l++) {
        if (l > 0) k_up<<<kN / 4, 256>>>(Wups + l * 4096, Wupv + l * 4096);
        k_edge<<<EGRID, 512, EDGE_SMEM>>>(Wr1 + l * 512, br1 + l * 64,   // 6 on l=0
                                          Wr2 + l * 4096, br2 + l * 64,
                                          Wr3 + l * 16384);
        k_node<<<kN / 4, 256, NODE_SMEM>>>(Wms + l * 4096, Wmv + l * 4096,
                                           Wscs + l * 32768, Wscv + l * 32768,
                                           Wps + l * 4096, Wpv + l * 4096,
                                           Wread + l * 192, l);
    }
    k_final<<<(kN + 255) / 256, 256>>>(out);
}

// round 5
// speedup vs baseline: 3.1548x; 1.0051x over previous
#include <cuda_runtime.h>
#include <math.h>

constexpr int kN  = 20000;
constexpr int kG  = 8;
constexpr int kE  = 640000;
constexpr int kC  = 64;
constexpr int kNB = 8;
constexpr int kL  = 3;
constexpr int TE  = 128;
constexpr int NTILE = kE / TE;
constexpr int EGRID = 152;

// ---------------- device scratch ----------------
__device__ float g_ef[kE * kNB];      // sorted order
__device__ float g_y1[kE * 3];        // sorted order
__device__ float g_mask[kE];          // sorted order
__device__ int   g_snd[kE];           // original order
__device__ int   g_rcv[kE];           // original order
__device__ int   g_psnd[kE];          // sorted
__device__ int   g_prcv[kE];          // sorted
__device__ int   g_slot[kE];
__device__ int   g_cnt[kN];           // zero-initialized; scan re-zeroes each run
__device__ int   g_base[kN];
__device__ int   g_sp[kN];
__device__ int   g_batch[kN];
__device__ float g_s[kN * kC];
__device__ float g_xf[kN * kC];
__device__ float g_xfs[8 * kC];
__device__ float g_sup0[8 * kC];
__device__ float g_v[kN * kC * 3];
__device__ float g_supv[kN * kC * 4];
__device__ float g_agg[kN * kC * 4];
__device__ float g_outs[kL * kN * 9];

typedef unsigned long long ull;

__device__ __forceinline__ float silu_f(float x) {
    return __fdividef(x, 1.0f + __expf(-x));
}
__device__ __forceinline__ ull pack2(float lo, float hi) {
    ull r; asm("mov.b64 %0,{%1,%2};" : "=l"(r) : "f"(lo), "f"(hi)); return r;
}
__device__ __forceinline__ void unpack2(ull v, float& lo, float& hi) {
    asm("mov.b64 {%0,%1},%2;" : "=f"(lo), "=f"(hi) : "l"(v));
}
__device__ __forceinline__ void fma2(ull& d, ull a, ull b) {
    asm("fma.rn.f32x2 %0,%1,%2,%0;" : "+l"(d) : "l"(a), "l"(b));
}
__device__ __forceinline__ void red4(float* p, float a, float b, float c, float d) {
    asm volatile("red.global.add.v4.f32 [%0],{%1,%2,%3,%4};"
                 :: "l"(p), "f"(a), "f"(b), "f"(c), "f"(d) : "memory");
}

// ---- launch 1: conv (per-block int-width detect) + degree count ----
__global__ void k_conv(const int* eraw, const int* braw, const int* spraw) {
    __shared__ int sf;
    if (threadIdx.x == 0) {
        int f = 1;
        for (int k = 0; k < 64; k++)
            if (spraw[2 * k + 1] != 0) { f = 0; break; }
        sf = f;
    }
    __syncthreads();
    int f = sf;
    int i = blockIdx.x * blockDim.x + threadIdx.x;
    if (i < kN) {
        g_batch[i] = f ? braw[2 * i] : braw[i];
        g_sp[i]    = f ? spraw[2 * i] : spraw[i];
    }
    if (i < kE) {
        int snd = f ? eraw[2 * i]        : eraw[i];
        int rcv = f ? eraw[2 * (kE + i)] : eraw[kE + i];
        g_snd[i] = snd;
        g_rcv[i] = rcv;
        g_slot[i] = atomicAdd(&g_cnt[rcv], 1);
    }
}

// ---- launch 2: scan counts (and re-zero), zero out, per-species tables ----
__global__ void k_scan(float* __restrict__ out,
                       const float* __restrict__ Wemb,
                       const float* __restrict__ Wx,
                       const float* __restrict__ Wups0) {
    __shared__ int buf[1024];
    __shared__ int carry;
    int tid = threadIdx.x;
    if (tid < 72) out[tid] = 0.0f;
    if (tid < 512) {
        int sp = tid >> 6, c = tid & 63;
        float a = 0.0f, b = 0.0f;
#pragma unroll 8
        for (int k = 0; k < kC; k++) {
            float w = Wemb[sp * kC + k];
            a += w * Wx[k * kC + c];
            b += w * Wups0[k * kC + c];
        }
        g_xfs[tid]  = a;
        g_sup0[tid] = b;
    }
    if (tid == 0) carry = 0;
    __syncthreads();
    for (int base = 0; base < kN; base += 1024) {
        int i = base + tid;
        int v = (i < kN) ? g_cnt[i] : 0;
        if (i < kN) g_cnt[i] = 0;          // restore for next replay
        buf[tid] = v;
        __syncthreads();
        for (int off = 1; off < 1024; off <<= 1) {
            int t = (tid >= off) ? buf[tid - off] : 0;
            __syncthreads();
            buf[tid] += t;
            __syncthreads();
        }
        if (i < kN) g_base[i] = carry + buf[tid] - v;
        __syncthreads();
        if (tid == 1023) carry += buf[1023];
        __syncthreads();
    }
}

// ---- launch 3: geometry (writes to sorted position) + node init fused ----
__global__ void k_geominit(const float* __restrict__ pos,
                           const float* __restrict__ cell,
                           const float* __restrict__ Sij,
                           const float* __restrict__ Wemb) {
    int t = blockIdx.x * blockDim.x + threadIdx.x;
    if (t < kE) {
        int e = t;
        int snd = g_snd[e], rcv = g_rcv[e];
        int p = g_base[rcv] + g_slot[e];
        g_psnd[p] = snd;
        g_prcv[p] = rcv;
        int b = g_batch[snd];
        float s0 = Sij[e * 3 + 0], s1 = Sij[e * 3 + 1], s2 = Sij[e * 3 + 2];
        const float* cb = cell + b * 9;
        float sh0 = s0 * cb[0] + s1 * cb[3] + s2 * cb[6];
        float sh1 = s0 * cb[1] + s1 * cb[4] + s2 * cb[7];
        float sh2 = s0 * cb[2] + s1 * cb[5] + s2 * cb[8];
        const float invcut = 1.0f / 6.0f;
        float r0 = (pos[rcv * 3 + 0] - pos[snd * 3 + 0] + sh0) * invcut;
        float r1 = (pos[rcv * 3 + 1] - pos[snd * 3 + 1] + sh1) * invcut;
        float r2 = (pos[rcv * 3 + 2] - pos[snd * 3 + 2] + sh2) * invcut;
        float len = sqrtf(r0 * r0 + r1 * r1 + r2 * r2);
        float mask = (len > 0.0f) ? 1.0f : 0.0f;
        float safe = (len > 0.0f) ? len : 1.0f;
        float inv = 1.0f / safe;
        const float sq3 = 1.7320508075688772f;
        g_y1[p * 3 + 0] = sq3 * r0 * inv;
        g_y1[p * 3 + 1] = sq3 * r1 * inv;
        g_y1[p * 3 + 2] = sq3 * r2 * inv;
        float x = safe;
        float env = (x < 1.0f) ? (1.0f - 6.0f * x * x + 8.0f * x * x * x - 3.0f * x * x * x * x) : 0.0f;
        float fac = 1.4142135623730951f * inv * env * mask;
        const float pi = 3.14159265358979323846f;
#pragma unroll
        for (int nb = 1; nb <= kNB; nb++)
            g_ef[p * kNB + nb - 1] = fac * sinf(pi * (float)nb * safe);
        g_mask[p] = mask;
    }
    if (t < kN * kC) {
        int n = t / kC, c = t % kC;
        int sp = g_sp[n];
        g_s[t]  = Wemb[sp * kC + c];
        g_xf[t] = g_xfs[sp * kC + c];
        g_v[n * 192 + c * 3 + 0] = 0.0f;
        g_v[n * 192 + c * 3 + 1] = 0.0f;
        g_v[n * 192 + c * 3 + 2] = 0.0f;
        *(float4*)&g_agg[t * 4] = make_float4(0.f, 0.f, 0.f, 0.f);
        *(float4*)&g_supv[t * 4] = make_float4(g_sup0[sp * kC + c], 0.f, 0.f, 0.f);
    }
}

// ---- up-projection (layers 1,2): 8 nodes per block ----
__global__ __launch_bounds__(512) void k_up(const float* __restrict__ Ws,
                                            const float* __restrict__ Wv) {
    __shared__ float sWs[4096], sWv[4096], ss[8][64], sv[8][192];
    int tid = threadIdx.x;
    for (int i = tid; i < 1024; i += 512) {
        ((float4*)sWs)[i] = ((const float4*)Ws)[i];
        ((float4*)sWv)[i] = ((const float4*)Wv)[i];
    }
    int slot = tid >> 6, o = tid & 63;
    int n = blockIdx.x * 8 + slot;
    ss[slot][o] = g_s[n * 64 + o];
    sv[slot][o * 3 + 0] = g_v[n * 192 + o * 3 + 0];
    sv[slot][o * 3 + 1] = g_v[n * 192 + o * 3 + 1];
    sv[slot][o * 3 + 2] = g_v[n * 192 + o * 3 + 2];
    __syncthreads();
    float su = 0.0f, v0 = 0.0f, v1 = 0.0f, v2 = 0.0f;
#pragma unroll 8
    for (int c = 0; c < 64; c++) {
        su += ss[slot][c] * sWs[c * 64 + o];
        float w = sWv[c * 64 + o];
        v0 += sv[slot][c * 3 + 0] * w;
        v1 += sv[slot][c * 3 + 1] * w;
        v2 += sv[slot][c * 3 + 2] * w;
    }
    *(float4*)&g_supv[n * 256 + o * 4] = make_float4(su, v0, v1, v2);
}

// ---- persistent edge kernel (dup-h SMEM, LDS.128 weights, merged scatter) ----
// floats: Wr1 512 | br 128 | Wr2 4096 | Wr3 16384 | h1d 2*TE*64 | h2d 2*TE*64
//         ef TE*8 | y TE*3 | mk TE | snd TE | rcv TE
constexpr int EDGE_SMEM = (512 + 128 + 4096 + 16384 + 2 * TE * 64 + 2 * TE * 64 +
                           TE * 8 + TE * 3 + TE + TE + TE) * 4;

__global__ __launch_bounds__(512, 1) void k_edge(const float* __restrict__ Wr1,
                                                 const float* __restrict__ br1,
                                                 const float* __restrict__ Wr2,
                                                 const float* __restrict__ br2,
                                                 const float* __restrict__ Wr3) {
    extern __shared__ float sm[];
    float* sWr1 = sm;                       // 512
    float* sbr1 = sWr1 + 512;               // 64
    float* sbr2 = sbr1 + 64;                // 64
    float* sWr2 = sbr2 + 64;                // 4096
    float* sWr3 = sWr2 + 4096;              // 16384
    ull*   sh1d = (ull*)(sWr3 + 16384);     // TE*64 ull
    ull*   sh2d = sh1d + TE * 64;           // TE*64 ull
    float* sef  = (float*)(sh2d + TE * 64); // TE*8
    float* sy   = sef + TE * 8;             // TE*3
    float* smk  = sy + TE * 3;              // TE
    int*   ssnd = (int*)(smk + TE);
    int*   srcv = ssnd + TE;

    int tid = threadIdx.x;
    for (int i = tid; i < 128; i += 512) ((float4*)sWr1)[i] = ((const float4*)Wr1)[i];
    if (tid < 64) { sbr1[tid] = br1[tid]; sbr2[tid] = br2[tid]; }
    for (int i = tid; i < 1024; i += 512) ((float4*)sWr2)[i] = ((const float4*)Wr2)[i];
    for (int i = tid; i < 4096; i += 512) ((float4*)sWr3)[i] = ((const float4*)Wr3)[i];

    int eg = tid >> 4;     // 0..31
    int cq = tid & 15;
    int c0 = cq * 4;
    int eb = eg * 4;

    const float inv_sqrt3 = 0.5773502691896258f;

    for (int tile = blockIdx.x; tile < NTILE; tile += EGRID) {
        int e0 = tile * TE;
        for (int i = tid; i < TE * 8; i += 512) sef[i] = g_ef[e0 * 8 + i];
        for (int i = tid; i < TE * 3; i += 512) sy[i]  = g_y1[e0 * 3 + i];
        if (tid < TE) {
            smk[tid]  = g_mask[e0 + tid] * 0.03125f;
            ssnd[tid] = g_psnd[e0 + tid];
            srcv[tid] = g_prcv[e0 + tid];
        }
        __syncthreads();

        // h1 = silu(ef @ Wr1 + br1), store duplicated pairs
        {
            ull acc[4][2];
            ull b0 = pack2(sbr1[c0], sbr1[c0 + 1]);
            ull b1 = pack2(sbr1[c0 + 2], sbr1[c0 + 3]);
#pragma unroll
            for (int i = 0; i < 4; i++) { acc[i][0] = b0; acc[i][1] = b1; }
#pragma unroll
            for (int k = 0; k < 8; k++) {
                ulonglong2 w = *(const ulonglong2*)&sWr1[k * 64 + c0];
#pragma unroll
                for (int i = 0; i < 4; i++) {
                    float h = sef[(eb + i) * 8 + k];
                    ull ha = pack2(h, h);
                    fma2(acc[i][0], ha, w.x);
                    fma2(acc[i][1], ha, w.y);
                }
            }
#pragma unroll
            for (int i = 0; i < 4; i++)
#pragma unroll
                for (int p = 0; p < 2; p++) {
                    float lo, hi; unpack2(acc[i][p], lo, hi);
                    float a = silu_f(lo), b = silu_f(hi);
                    sh1d[(eb + i) * 64 + c0 + 2 * p]     = pack2(a, a);
                    sh1d[(eb + i) * 64 + c0 + 2 * p + 1] = pack2(b, b);
                }
        }
        __syncthreads();

        // h2 = silu(h1 @ Wr2 + br2), store duplicated pairs
        {
            ull acc[4][2];
            ull b0 = pack2(sbr2[c0], sbr2[c0 + 1]);
            ull b1 = pack2(sbr2[c0 + 2], sbr2[c0 + 3]);
#pragma unroll
            for (int i = 0; i < 4; i++) { acc[i][0] = b0; acc[i][1] = b1; }
#pragma unroll 4
            for (int k = 0; k < 64; k++) {
                ulonglong2 w = *(const ulonglong2*)&sWr2[k * 64 + c0];
#pragma unroll
                for (int i = 0; i < 4; i++) {
                    ull ha = sh1d[(eb + i) * 64 + k];
                    fma2(acc[i][0], ha, w.x);
                    fma2(acc[i][1], ha, w.y);
                }
            }
#pragma unroll
            for (int i = 0; i < 4; i++)
#pragma unroll
                for (int p = 0; p < 2; p++) {
                    float lo, hi; unpack2(acc[i][p], lo, hi);
                    float a = silu_f(lo), b = silu_f(hi);
                    sh2d[(eb + i) * 64 + c0 + 2 * p]     = pack2(a, a);
                    sh2d[(eb + i) * 64 + c0 + 2 * p + 1] = pack2(b, b);
                }
        }
        __syncthreads();

        // wts = h2 @ Wr3
        ull acc3[4][4][2];
#pragma unroll
        for (int i = 0; i < 4; i++)
#pragma unroll
            for (int t = 0; t < 4; t++) { acc3[i][t][0] = 0ULL; acc3[i][t][1] = 0ULL; }

#pragma unroll 2
        for (int k = 0; k < 64; k++) {
            ull ha[4];
#pragma unroll
            for (int i = 0; i < 4; i++) ha[i] = sh2d[(eb + i) * 64 + k];
            const float* wr = &sWr3[k * 256 + c0];
#pragma unroll
            for (int t = 0; t < 4; t++) {
                ulonglong2 w = *(const ulonglong2*)(wr + t * 64);
#pragma unroll
                for (int i = 0; i < 4; i++) {
                    fma2(acc3[i][t][0], ha[i], w.x);
                    fma2(acc3[i][t][1], ha[i], w.y);
                }
            }
        }

        // messages with register-merged scatter (edges sorted by rcv)
        {
            int cur = -1;
            float aq[4][4];
#pragma unroll
            for (int i = 0; i < 4; i++) {
                int le = eb + i;
                int rcv = srcv[le];
                if (rcv != cur) {
                    if (cur >= 0) {
                        float* agp = &g_agg[cur * 256];
#pragma unroll
                        for (int q = 0; q < 4; q++)
                            red4(agp + (c0 + q) * 4, aq[q][0], aq[q][1], aq[q][2], aq[q][3]);
                    }
                    cur = rcv;
#pragma unroll
                    for (int q = 0; q < 4; q++)
                        aq[q][0] = aq[q][1] = aq[q][2] = aq[q][3] = 0.0f;
                }
                float msk = smk[le];
                float y0 = sy[le * 3 + 0], y1v = sy[le * 3 + 1], y2 = sy[le * 3 + 2];
                int snd = ssnd[le];
                const float4* svp = (const float4*)&g_supv[snd * 256];
#pragma unroll
                for (int p = 0; p < 2; p++) {
                    float wt[4][2];
#pragma unroll
                    for (int t = 0; t < 4; t++) unpack2(acc3[i][t][p], wt[t][0], wt[t][1]);
#pragma unroll
                    for (int jj = 0; jj < 2; jj++) {
                        int q = 2 * p + jj;
                        float w0 = wt[0][jj] * msk, w1 = wt[1][jj] * msk;
                        float w2 = wt[2][jj] * msk, w3 = wt[3][jj] * msk;
                        float4 s4 = svp[c0 + q];
                        float dot = (s4.y * y0 + s4.z * y1v + s4.w * y2) * inv_sqrt3;
                        float a0 = w2 * s4.x;
                        aq[q][0] += w0 * s4.x + w1 * dot;
                        aq[q][1] += a0 * y0  + w3 * s4.y;
                        aq[q][2] += a0 * y1v + w3 * s4.z;
                        aq[q][3] += a0 * y2  + w3 * s4.w;
                    }
                }
            }
            if (cur >= 0) {
                float* agp = &g_agg[cur * 256];
#pragma unroll
                for (int q = 0; q < 4; q++)
                    red4(agp + (c0 + q) * 4, aq[q][0], aq[q][1], aq[q][2], aq[q][3]);
            }
        }
        __syncthreads();
    }
}

// ---- node update (8 nodes/block; zeroes g_agg for next layer) ----
constexpr int NODE_SMEM = (4 * 4096 + 8 * (256 + 64 + 192 + 64 + 192 + 192)) * 4;

__global__ __launch_bounds__(512) void k_node(const float* __restrict__ Wms,
                                              const float* __restrict__ Wmv,
                                              const float* __restrict__ Wscs,
                                              const float* __restrict__ Wscv,
                                              const float* __restrict__ Wps,
                                              const float* __restrict__ Wpv,
                                              const float* __restrict__ Wread, int l) {
    extern __shared__ float sm[];
    float* sWms = sm;
    float* sWmv = sWms + 4096;
    float* sWps = sWmv + 4096;
    float* sWpv = sWps + 4096;
    float* sagg = sWpv + 4096;        // [8][256]
    float* sold = sagg + 8 * 256;     // [8][64]
    float* vold = sold + 8 * 64;      // [8][192]
    float* sts  = vold + 8 * 192;     // [8][64]
    float* stv  = sts + 8 * 64;       // [8][192]
    float* vnew = stv + 8 * 192;      // [8][192]

    int tid = threadIdx.x;
    for (int i = tid; i < 1024; i += 512) {
        ((float4*)sWms)[i] = ((const float4*)Wms)[i];
        ((float4*)sWmv)[i] = ((const float4*)Wmv)[i];
        ((float4*)sWps)[i] = ((const float4*)Wps)[i];
        ((float4*)sWpv)[i] = ((const float4*)Wpv)[i];
    }
    int slot = tid >> 6, o = tid & 63;
    int n = blockIdx.x * 8 + slot;
    *(float4*)&sagg[slot * 256 + o * 4] = *(const float4*)&g_agg[n * 256 + o * 4];
    *(float4*)&g_agg[n * 256 + o * 4] = make_float4(0.f, 0.f, 0.f, 0.f);
    sold[slot * 64 + o] = g_s[n * 64 + o];
    vold[slot * 192 + o * 3 + 0] = g_v[n * 192 + o * 3 + 0];
    vold[slot * 192 + o * 3 + 1] = g_v[n * 192 + o * 3 + 1];
    vold[slot * 192 + o * 3 + 2] = g_v[n * 192 + o * 3 + 2];
    __syncthreads();

    int sp = g_sp[n];
    const float* Wss = Wscs + sp * 4096;
    const float* Wsv = Wscv + sp * 4096;

    float ms = 0, mv0 = 0, mv1 = 0, mv2 = 0;
    float scs = 0, scv0 = 0, scv1 = 0, scv2 = 0;
#pragma unroll 4
    for (int c = 0; c < 64; c++) {
        const float* ag = &sagg[slot * 256 + c * 4];
        ms  += ag[0] * sWms[c * 64 + o];
        float wm = sWmv[c * 64 + o];
        mv0 += ag[1] * wm; mv1 += ag[2] * wm; mv2 += ag[3] * wm;
        scs += sold[slot * 64 + c] * Wss[c * 64 + o];
        float wv = Wsv[c * 64 + o];
        scv0 += vold[slot * 192 + c * 3 + 0] * wv;
        scv1 += vold[slot * 192 + c * 3 + 1] * wv;
        scv2 += vold[slot * 192 + c * 3 + 2] * wv;
    }
    float xfo = g_xf[n * 64 + o];
    sts[slot * 64 + o] = xfo * ms;
    stv[slot * 192 + o * 3 + 0] = xfo * mv0;
    stv[slot * 192 + o * 3 + 1] = xfo * mv1;
    stv[slot * 192 + o * 3 + 2] = xfo * mv2;
    __syncthreads();

    float sn = scs, vn0 = scv0, vn1 = scv1, vn2 = scv2;
#pragma unroll 4
    for (int c = 0; c < 64; c++) {
        sn += sts[slot * 64 + c] * sWps[c * 64 + o];
        float wp = sWpv[c * 64 + o];
        vn0 += stv[slot * 192 + c * 3 + 0] * wp;
        vn1 += stv[slot * 192 + c * 3 + 1] * wp;
        vn2 += stv[slot * 192 + c * 3 + 2] * wp;
    }
    g_s[n * 64 + o] = sn;
    g_v[n * 192 + o * 3 + 0] = vn0;
    g_v[n * 192 + o * 3 + 1] = vn1;
    g_v[n * 192 + o * 3 + 2] = vn2;
    vnew[slot * 192 + o * 3 + 0] = vn0;
    vnew[slot * 192 + o * 3 + 1] = vn1;
    vnew[slot * 192 + o * 3 + 2] = vn2;
    __syncthreads();

    if (o < 9) {
        int ro = o / 3, m = o % 3;
        float a = 0.0f;
#pragma unroll 8
        for (int c = 0; c < 64; c++) a += vnew[slot * 192 + c * 3 + m] * Wread[ro * 64 + c];
        g_outs[l * kN * 9 + n * 9 + o] = a;
    }
}

// ---- final reduce ----
__global__ void k_final(float* __restrict__ out) {
    __shared__ float acc[72];
    int tid = threadIdx.x;
    if (tid < 72) acc[tid] = 0.0f;
    __syncthreads();
    int n = blockIdx.x * blockDim.x + tid;
    if (n < kN) {
        int b = g_batch[n];
#pragma unroll
        for (int j = 0; j < 9; j++) {
            float x = 0.0f;
#pragma unroll
            for (int l = 0; l < kL; l++) x += silu_f(g_outs[l * kN * 9 + n * 9 + j]);
            atomicAdd(&acc[b * 9 + j], x);
        }
    }
    __syncthreads();
    if (tid < 72) atomicAdd(&out[tid], acc[tid]);
}

// ---- launch ----
extern "C" void kernel_launch(void* const* d_in, const int* in_sizes, int n_in,
                              void* d_out, int out_size) {
    const float* pos  = (const float*)d_in[0];
    const float* cell = (const float*)d_in[1];
    const float* Sij  = (const float*)d_in[2];
    const float* Wemb = (const float*)d_in[3];
    const float* Wx   = (const float*)d_in[4];
    const float* Wups = (const float*)d_in[5];
    const float* Wupv = (const float*)d_in[6];
    const float* Wr1  = (const float*)d_in[7];
    const float* br1  = (const float*)d_in[8];
    const float* Wr2  = (const float*)d_in[9];
    const float* br2  = (const float*)d_in[10];
    const float* Wr3  = (const float*)d_in[11];
    const float* Wms  = (const float*)d_in[12];
    const float* Wmv  = (const float*)d_in[13];
    const float* Wscs = (const float*)d_in[14];
    const float* Wscv = (const float*)d_in[15];
    const float* Wps  = (const float*)d_in[16];
    const float* Wpv  = (const float*)d_in[17];
    const float* Wread= (const float*)d_in[18];
    const int* ei     = (const int*)d_in[19];
    const int* braw   = (const int*)d_in[20];
    const int* spraw  = (const int*)d_in[21];
    float* out = (float*)d_out;

    cudaFuncSetAttribute(k_edge, cudaFuncAttributeMaxDynamicSharedMemorySize, EDGE_SMEM);
    cudaFuncSetAttribute(k_node, cudaFuncAttributeMaxDynamicSharedMemorySize, NODE_SMEM);

    k_conv<<<(kE + 255) / 256, 256>>>(ei, braw, spraw);                  // 1
    k_scan<<<1, 1024>>>(out, Wemb, Wx, Wups);                            // 2
    k_geominit<<<(kN * kC + 255) / 256, 256>>>(pos, cell, Sij, Wemb);    // 3

    for (int l = 0; l < kL; l++) {
        if (l > 0) k_up<<<kN / 8, 512>>>(Wups + l * 4096, Wupv + l * 4096);
        k_edge<<<EGRID, 512, EDGE_SMEM>>>(Wr1 + l * 512, br1 + l * 64,   // 4 on l=0
                                          Wr2 + l * 4096, br2 + l * 64,
                                          Wr3 + l * 16384);
        k_node<<<kN / 8, 512, NODE_SMEM>>>(Wms + l * 4096, Wmv + l * 4096,
                                           Wscs + l * 32768, Wscv + l * 32768,
                                           Wps + l * 4096, Wpv + l * 4096,
                                           Wread + l * 192, l);
    }
    k_final<<<(kN + 255) / 256, 256>>>(out);
}